// round 7
// baseline (speedup 1.0000x reference)
#include <cuda_runtime.h>
#include <cuda_fp16.h>

#define BB 4
#define SS 1024
#define EE 1024
#define HH 16
#define DD 64
#define NQ 32            // queries per fused block
#define SCALE 0.125f     // 1/sqrt(64)
#define NBLK (BB * (SS / NQ))   // 128 fused blocks

// 4-byte grid-barrier counter: monotonic across replays (target = next
// multiple of NBLK), so it never needs resetting.
__device__ unsigned int g_bar;

__device__ __forceinline__ float neg_inf() { return __int_as_float(0xff800000); }

// fused kernel dynamic smem layout (bytes):
//   s_scores : 32*1024 f32 = 131072   (also Wo staging in phase B)
//   s_ctx    : 32*1024 f16 =  65536
//   s_kv     : 64*68   f32 =  17408
//   s_q      : 32*68   f32 =   8704
//   s_keep   : 1024    f32 =   4096
#define FUSED_SMEM (131072 + 65536 + 17408 + 8704 + 4096)   // 226816 <= 227KB

// ============================================================================
// P1: K/V projection -> fp16 into the (currently dead) output region.
// grid.x = which(2)*16 s-tiles, grid.y = h, grid.z = b. 256 threads.
// K at kv[0 .. 4M), V at kv[4M .. 8M) halves, each (B,H,S,D).
// ============================================================================
__global__ void kv_proj_kernel(const float* __restrict__ key,
                               const float* __restrict__ value,
                               const float* __restrict__ in_w,
                               const float* __restrict__ in_b,
                               __half* __restrict__ kv)
{
    __shared__ float As[16][68];
    __shared__ float Bs[16][68];

    const int which = blockIdx.x >> 4;            // 0=k, 1=v
    const int s0 = (blockIdx.x & 15) * 64;
    const int h = blockIdx.y, b = blockIdx.z;
    const float* X = (which ? value : key) + (size_t)b * SS * EE;
    const int woff = (which ? 2048 : 1024) + h * 64;

    const int tid = threadIdx.x;
    const int tx = tid & 15, ty = tid >> 4;
    const int lr = tid >> 2, lc = tid & 3;

    float acc[4][4];
    #pragma unroll
    for (int i = 0; i < 4; i++)
        #pragma unroll
        for (int j = 0; j < 4; j++) acc[i][j] = 0.0f;

    for (int k0 = 0; k0 < 1024; k0 += 16) {
        float4 a = *(const float4*)&X[(size_t)(s0 + lr) * 1024 + k0 + lc * 4];
        float4 w = *(const float4*)&in_w[(size_t)(woff + lr) * 1024 + k0 + lc * 4];
        As[lc*4+0][lr] = a.x; As[lc*4+1][lr] = a.y;
        As[lc*4+2][lr] = a.z; As[lc*4+3][lr] = a.w;
        Bs[lc*4+0][lr] = w.x; Bs[lc*4+1][lr] = w.y;
        Bs[lc*4+2][lr] = w.z; Bs[lc*4+3][lr] = w.w;
        __syncthreads();

        #pragma unroll
        for (int kk = 0; kk < 16; kk++) {
            float4 ra = *(const float4*)&As[kk][ty * 4];
            float4 rb = *(const float4*)&Bs[kk][tx * 4];
            float va[4] = {ra.x, ra.y, ra.z, ra.w};
            float vb[4] = {rb.x, rb.y, rb.z, rb.w};
            #pragma unroll
            for (int i = 0; i < 4; i++)
                #pragma unroll
                for (int j = 0; j < 4; j++)
                    acc[i][j] = fmaf(va[i], vb[j], acc[i][j]);
        }
        __syncthreads();
    }

    __half* dst = kv + (size_t)which * (BB*HH*SS*DD)
                     + ((size_t)(b * HH + h) * SS) * DD;
    #pragma unroll
    for (int i = 0; i < 4; i++) {
        const int s = s0 + ty * 4 + i;
        #pragma unroll
        for (int j = 0; j < 4; j++) {
            const int d = tx * 4 + j;
            dst[(size_t)s * DD + d] = __float2half(acc[i][j] + in_b[woff + d]);
        }
    }
}

// ============================================================================
// P2: fused attention + output projection. grid (32 qt, 4 b), 256 threads.
// MASK: read as 32-bit words (bool is promoted to int32/float32 by the
// harness — both give word!=0 <=> keep). NOT as bytes.
// ============================================================================
__global__ void __launch_bounds__(256, 1)
fused_attn_kernel(const float* __restrict__ query,
                  const float* __restrict__ in_w,
                  const float* __restrict__ in_b,
                  const unsigned int* __restrict__ mask_w,
                  const __half* __restrict__ kv,
                  const float* __restrict__ out_w,
                  const float* __restrict__ out_b,
                  float* __restrict__ mean_out,
                  float* __restrict__ out)
{
    extern __shared__ float smem[];
    float*  s_scores = smem;                                  // 32*1024 f32
    __half* s_ctx    = (__half*)(smem + 32 * 1024);           // 32*1024 f16
    float*  s_kv     = (float*)((char*)s_ctx + 32*1024*2);    // 64*68
    float*  s_q      = s_kv + 64 * 68;                        // 32*68
    float*  s_keep   = s_q + 32 * 68;                         // 1024

    const int qt = blockIdx.x, b = blockIdx.y;
    const int q0 = qt * NQ;
    const int tid = threadIdx.x;

    for (int i = tid; i < 1024; i += 256)
        s_keep[i] = (mask_w[b * SS + i] != 0u) ? 1.0f : 0.0f;

    const int kj = tid & 63;        // k index within 64-tile
    const int qb = tid >> 6;        // base q (0..3), qi = qb + 4*j
    const int row = tid >> 3;       // softmax row
    const int lane = tid & 7;       // softmax lane

    // ==================== Phase A: heads loop ====================
    for (int h = 0; h < HH; h++) {
        const __half* Kb = kv + ((size_t)(b * HH + h) * SS) * DD;
        const __half* Vb = Kb + (size_t)(BB*HH*SS*DD);

        // ---- q tile = query[b, q0:q0+32, :] @ wq_h^T + bq_h ----
        {
            float* qS = s_scores;                 // [32][68]
            float* wT = s_scores + 32 * 68;       // [64][68], [k][j]
            const int r8 = tid >> 3, cb = tid & 7;
            float acc8[8];
            #pragma unroll
            for (int j = 0; j < 8; j++) acc8[j] = 0.0f;

            for (int e0 = 0; e0 < 1024; e0 += 64) {
                __syncthreads();
                for (int i = tid; i < 32 * 16; i += 256) {
                    const int r = i >> 4, c4 = i & 15;
                    *(float4*)&qS[r * 68 + c4 * 4] =
                        *(const float4*)&query[((size_t)(b * SS) + q0 + r) * 1024 + e0 + c4 * 4];
                }
                for (int i = tid; i < 64 * 16; i += 256) {
                    const int j = i >> 4, c4 = i & 15;
                    float4 w = *(const float4*)&in_w[(size_t)(h * 64 + j) * 1024 + e0 + c4 * 4];
                    wT[(c4*4+0) * 68 + j] = w.x;
                    wT[(c4*4+1) * 68 + j] = w.y;
                    wT[(c4*4+2) * 68 + j] = w.z;
                    wT[(c4*4+3) * 68 + j] = w.w;
                }
                __syncthreads();

                #pragma unroll 8
                for (int kk = 0; kk < 64; kk++) {
                    const float qv = qS[r8 * 68 + kk];
                    const float4 w0 = *(const float4*)&wT[kk * 68 + cb * 8];
                    const float4 w1 = *(const float4*)&wT[kk * 68 + cb * 8 + 4];
                    acc8[0] = fmaf(qv, w0.x, acc8[0]);
                    acc8[1] = fmaf(qv, w0.y, acc8[1]);
                    acc8[2] = fmaf(qv, w0.z, acc8[2]);
                    acc8[3] = fmaf(qv, w0.w, acc8[3]);
                    acc8[4] = fmaf(qv, w1.x, acc8[4]);
                    acc8[5] = fmaf(qv, w1.y, acc8[5]);
                    acc8[6] = fmaf(qv, w1.z, acc8[6]);
                    acc8[7] = fmaf(qv, w1.w, acc8[7]);
                }
            }
            __syncthreads();
            #pragma unroll
            for (int j = 0; j < 8; j++) {
                const int col = cb * 8 + j;
                s_q[r8 * 68 + col] = acc8[j] + in_b[h * 64 + col];
            }
        }

        // ---- scores ----
        for (int kt = 0; kt < 16; kt++) {
            __syncthreads();
            for (int i = tid; i < 64 * 32; i += 256) {
                const int r = i >> 5, c2 = i & 31;
                const __half2 hv = *(const __half2*)&Kb[(size_t)(kt * 64 + r) * DD + c2 * 2];
                const float2 fv = __half22float2(hv);
                s_kv[r * 68 + c2 * 2]     = fv.x;
                s_kv[r * 68 + c2 * 2 + 1] = fv.y;
            }
            __syncthreads();

            float acc[8];
            #pragma unroll
            for (int j = 0; j < 8; j++) acc[j] = 0.0f;

            #pragma unroll
            for (int d4 = 0; d4 < 16; d4++) {
                const float4 kvv = *(const float4*)&s_kv[kj * 68 + d4 * 4];
                #pragma unroll
                for (int j = 0; j < 8; j++) {
                    const int qi = qb + j * 4;
                    const float4 qv = *(const float4*)&s_q[qi * 68 + d4 * 4];
                    acc[j] = fmaf(qv.x, kvv.x, acc[j]);
                    acc[j] = fmaf(qv.y, kvv.y, acc[j]);
                    acc[j] = fmaf(qv.z, kvv.z, acc[j]);
                    acc[j] = fmaf(qv.w, kvv.w, acc[j]);
                }
            }

            const int kg = kt * 64 + kj;
            const float keep = s_keep[kg];
            #pragma unroll
            for (int j = 0; j < 8; j++) {
                const int qi = qb + j * 4;
                float sc = acc[j] * SCALE + (float)(q0 + qi - kg);
                sc = (keep != 0.0f) ? sc : neg_inf();
                s_scores[qi * 1024 + kg] = sc;
            }
        }
        __syncthreads();

        // ---- softmax + direct mean write/accumulate ----
        {
            float* srow = s_scores + row * 1024;

            float mx = neg_inf();
            for (int c = lane; c < 1024; c += 8) mx = fmaxf(mx, srow[c]);
            #pragma unroll
            for (int m = 1; m < 8; m <<= 1)
                mx = fmaxf(mx, __shfl_xor_sync(0xffffffffu, mx, m, 8));

            float sum = 0.0f;
            for (int c = lane; c < 1024; c += 8) {
                const float p = __expf(srow[c] - mx);
                srow[c] = p;
                sum += p;
            }
            #pragma unroll
            for (int m = 1; m < 8; m <<= 1)
                sum += __shfl_xor_sync(0xffffffffu, sum, m, 8);

            const float inv = 1.0f / sum;
            float* mrow = mean_out + ((size_t)(b * SS) + q0 + row) * SS;
            if (h == 0) {
                for (int c = lane; c < 1024; c += 8) {
                    const float p = srow[c] * inv;
                    srow[c] = p;
                    mrow[c] = p * 0.0625f;
                }
            } else {
                for (int c = lane; c < 1024; c += 8) {
                    const float p = srow[c] * inv;
                    srow[c] = p;
                    mrow[c] += p * 0.0625f;
                }
            }
        }

        // ---- ctx tile = P @ V -> smem fp16 (cols h*64 .. h*64+63) ----
        {
            const int d = tid & 63;
            float cacc[8];
            #pragma unroll
            for (int j = 0; j < 8; j++) cacc[j] = 0.0f;

            for (int kt = 0; kt < 16; kt++) {
                __syncthreads();
                for (int i = tid; i < 64 * 32; i += 256) {
                    const int r = i >> 5, c2 = i & 31;
                    const __half2 hv = *(const __half2*)&Vb[(size_t)(kt * 64 + r) * DD + c2 * 2];
                    const float2 fv = __half22float2(hv);
                    s_kv[r * 68 + c2 * 2]     = fv.x;
                    s_kv[r * 68 + c2 * 2 + 1] = fv.y;
                }
                __syncthreads();

                #pragma unroll 4
                for (int kk = 0; kk < 64; kk++) {
                    const float v = s_kv[kk * 68 + d];
                    const int kg = kt * 64 + kk;
                    #pragma unroll
                    for (int j = 0; j < 8; j++) {
                        const int qi = qb + j * 4;
                        cacc[j] = fmaf(s_scores[qi * 1024 + kg], v, cacc[j]);
                    }
                }
            }

            #pragma unroll
            for (int j = 0; j < 8; j++) {
                const int qi = qb + j * 4;
                s_ctx[qi * 1024 + h * 64 + d] = __float2half(cacc[j]);
            }
        }
        __syncthreads();
    }

    // ==================== grid barrier ====================
    // All 128 blocks co-resident (1 block/SM). Monotonic counter: target is
    // the next multiple of NBLK, so replays need no reset.
    if (tid == 0) {
        __threadfence();
        const unsigned int old = atomicAdd(&g_bar, 1u);
        const unsigned int target = (old / NBLK + 1u) * NBLK;
        while (atomicAdd(&g_bar, 0u) < target) { }
    }
    __syncthreads();

    // ==================== Phase B: out tile = ctx @ Wo^T + bias ====================
    {
        const int r2 = tid >> 4;     // rows r2*2, r2*2+1
        const int c16 = tid & 15;    // cols c16*4 .. +3
        float* wS = s_scores;        // staging [256][68] (scores dead)

        for (int n0 = 0; n0 < 1024; n0 += 64) {
            float acc[2][4];
            #pragma unroll
            for (int i = 0; i < 2; i++)
                #pragma unroll
                for (int j = 0; j < 4; j++) acc[i][j] = 0.0f;

            for (int k0 = 0; k0 < 1024; k0 += 256) {
                __syncthreads();
                for (int i = tid; i < 64 * 64; i += 256) {
                    const int nn = i >> 6;
                    const int k4 = i & 63;
                    float4 w = *(const float4*)&out_w[(size_t)(n0 + nn) * 1024 + k0 + k4 * 4];
                    wS[(k4*4+0) * 68 + nn] = w.x;
                    wS[(k4*4+1) * 68 + nn] = w.y;
                    wS[(k4*4+2) * 68 + nn] = w.z;
                    wS[(k4*4+3) * 68 + nn] = w.w;
                }
                __syncthreads();

                #pragma unroll 4
                for (int kk = 0; kk < 256; kk++) {
                    const float a0 = __half2float(s_ctx[(r2*2 + 0) * 1024 + k0 + kk]);
                    const float a1 = __half2float(s_ctx[(r2*2 + 1) * 1024 + k0 + kk]);
                    const float4 wv = *(const float4*)&wS[kk * 68 + c16 * 4];
                    acc[0][0] = fmaf(a0, wv.x, acc[0][0]);
                    acc[0][1] = fmaf(a0, wv.y, acc[0][1]);
                    acc[0][2] = fmaf(a0, wv.z, acc[0][2]);
                    acc[0][3] = fmaf(a0, wv.w, acc[0][3]);
                    acc[1][0] = fmaf(a1, wv.x, acc[1][0]);
                    acc[1][1] = fmaf(a1, wv.y, acc[1][1]);
                    acc[1][2] = fmaf(a1, wv.z, acc[1][2]);
                    acc[1][3] = fmaf(a1, wv.w, acc[1][3]);
                }
            }

            #pragma unroll
            for (int i = 0; i < 2; i++) {
                const int r = r2 * 2 + i;
                #pragma unroll
                for (int j = 0; j < 4; j++) {
                    const int n = n0 + c16 * 4 + j;
                    out[((size_t)(b * SS) + q0 + r) * 1024 + n] = acc[i][j] + out_b[n];
                }
            }
        }
    }
}

// ============================================================================
extern "C" void kernel_launch(void* const* d_in, const int* in_sizes, int n_in,
                              void* d_out, int out_size)
{
    const float* query = (const float*)d_in[0];
    const float* key   = (const float*)d_in[1];
    const float* value = (const float*)d_in[2];
    const unsigned int* mask_w = (const unsigned int*)d_in[3];  // bool promoted to i32/f32
    const float* in_w  = (const float*)d_in[4];
    const float* in_b  = (const float*)d_in[5];
    const float* out_w = (const float*)d_in[6];
    const float* out_b = (const float*)d_in[7];

    float* out      = (float*)d_out;                 // (B,S,E); holds kv fp16 until phase B
    float* mean_out = out + (size_t)BB * SS * EE;    // (B,S,S)
    __half* kv      = (__half*)d_out;                // K at [0], V at [+4M halves]

    cudaFuncSetAttribute(fused_attn_kernel,
                         cudaFuncAttributeMaxDynamicSharedMemorySize, FUSED_SMEM);

    // 1. K/V projection -> fp16 into the (dead) output region
    kv_proj_kernel<<<dim3(32, HH, BB), 256>>>(key, value, in_w, in_b, kv);

    // 2. fused attention + out-projection (writes mean directly, then output)
    fused_attn_kernel<<<dim3(SS / NQ, BB), 256, FUSED_SMEM>>>(
        query, in_w, in_b, mask_w, kv, out_w, out_b, mean_out, out);
}

// round 8
// speedup vs baseline: 1.0012x; 1.0012x over previous
#include <cuda_runtime.h>
#include <cuda_fp16.h>

#define BB 4
#define SS 1024
#define EE 1024
#define HH 16
#define DD 64
#define NQ 32            // queries per fused block
#define SCALE 0.125f     // 1/sqrt(64)
#define NBLK (BB * (SS / NQ))   // 128 fused blocks

// 4-byte grid-barrier counter: monotonic across replays (target = next
// multiple of NBLK), so it never needs resetting.
__device__ unsigned int g_bar;

__device__ __forceinline__ float neg_inf() { return __int_as_float(0xff800000); }

// fused kernel dynamic smem layout (bytes):
//   s_scores : 32*1024 f32 = 131072   (also Wo staging in phase B)
//   s_ctx    : 32*1024 f16 =  65536
//   s_kv     : 64*68   f32 =  17408
//   s_q      : 32*68   f32 =   8704
//   s_keep   : 1024    f32 =   4096
#define FUSED_SMEM (131072 + 65536 + 17408 + 8704 + 4096)   // 226816 <= 227KB

// ============================================================================
// P1: K/V projection -> fp16 into the (currently dead) output region.
// grid.x = which(2)*16 s-tiles, grid.y = h, grid.z = b. 256 threads.
// K at kv[0 .. 4M), V at kv[4M .. 8M) halves, each (B,H,S,D).
// ============================================================================
__global__ void kv_proj_kernel(const float* __restrict__ key,
                               const float* __restrict__ value,
                               const float* __restrict__ in_w,
                               const float* __restrict__ in_b,
                               __half* __restrict__ kv)
{
    __shared__ float As[16][68];
    __shared__ float Bs[16][68];

    const int which = blockIdx.x >> 4;            // 0=k, 1=v
    const int s0 = (blockIdx.x & 15) * 64;
    const int h = blockIdx.y, b = blockIdx.z;
    const float* X = (which ? value : key) + (size_t)b * SS * EE;
    const int woff = (which ? 2048 : 1024) + h * 64;

    const int tid = threadIdx.x;
    const int tx = tid & 15, ty = tid >> 4;
    const int lr = tid >> 2, lc = tid & 3;

    float acc[4][4];
    #pragma unroll
    for (int i = 0; i < 4; i++)
        #pragma unroll
        for (int j = 0; j < 4; j++) acc[i][j] = 0.0f;

    for (int k0 = 0; k0 < 1024; k0 += 16) {
        float4 a = *(const float4*)&X[(size_t)(s0 + lr) * 1024 + k0 + lc * 4];
        float4 w = *(const float4*)&in_w[(size_t)(woff + lr) * 1024 + k0 + lc * 4];
        As[lc*4+0][lr] = a.x; As[lc*4+1][lr] = a.y;
        As[lc*4+2][lr] = a.z; As[lc*4+3][lr] = a.w;
        Bs[lc*4+0][lr] = w.x; Bs[lc*4+1][lr] = w.y;
        Bs[lc*4+2][lr] = w.z; Bs[lc*4+3][lr] = w.w;
        __syncthreads();

        #pragma unroll
        for (int kk = 0; kk < 16; kk++) {
            float4 ra = *(const float4*)&As[kk][ty * 4];
            float4 rb = *(const float4*)&Bs[kk][tx * 4];
            float va[4] = {ra.x, ra.y, ra.z, ra.w};
            float vb[4] = {rb.x, rb.y, rb.z, rb.w};
            #pragma unroll
            for (int i = 0; i < 4; i++)
                #pragma unroll
                for (int j = 0; j < 4; j++)
                    acc[i][j] = fmaf(va[i], vb[j], acc[i][j]);
        }
        __syncthreads();
    }

    __half* dst = kv + (size_t)which * (BB*HH*SS*DD)
                     + ((size_t)(b * HH + h) * SS) * DD;
    #pragma unroll
    for (int i = 0; i < 4; i++) {
        const int s = s0 + ty * 4 + i;
        #pragma unroll
        for (int j = 0; j < 4; j++) {
            const int d = tx * 4 + j;
            dst[(size_t)s * DD + d] = __float2half(acc[i][j] + in_b[woff + d]);
        }
    }
}

// ============================================================================
// P2: fused attention + output projection. grid (32 qt, 4 b), 256 threads.
// MASK: read as 32-bit words (bool is promoted to int32/float32 by the
// harness — both give word!=0 <=> keep). NOT as bytes.
// ============================================================================
__global__ void __launch_bounds__(256, 1)
fused_attn_kernel(const float* __restrict__ query,
                  const float* __restrict__ in_w,
                  const float* __restrict__ in_b,
                  const unsigned int* __restrict__ mask_w,
                  const __half* __restrict__ kv,
                  const float* __restrict__ out_w,
                  const float* __restrict__ out_b,
                  float* __restrict__ mean_out,
                  float* __restrict__ out)
{
    extern __shared__ float smem[];
    float*  s_scores = smem;                                  // 32*1024 f32
    __half* s_ctx    = (__half*)(smem + 32 * 1024);           // 32*1024 f16
    float*  s_kv     = (float*)((char*)s_ctx + 32*1024*2);    // 64*68
    float*  s_q      = s_kv + 64 * 68;                        // 32*68
    float*  s_keep   = s_q + 32 * 68;                         // 1024

    const int qt = blockIdx.x, b = blockIdx.y;
    const int q0 = qt * NQ;
    const int tid = threadIdx.x;

    for (int i = tid; i < 1024; i += 256)
        s_keep[i] = (mask_w[b * SS + i] != 0u) ? 1.0f : 0.0f;

    const int kj = tid & 63;        // k index within 64-tile
    const int qb = tid >> 6;        // base q (0..3), qi = qb + 4*j
    const int row = tid >> 3;       // softmax row
    const int lane = tid & 7;       // softmax lane

    // ==================== Phase A: heads loop ====================
    for (int h = 0; h < HH; h++) {
        const __half* Kb = kv + ((size_t)(b * HH + h) * SS) * DD;
        const __half* Vb = Kb + (size_t)(BB*HH*SS*DD);

        // ---- q tile = query[b, q0:q0+32, :] @ wq_h^T + bq_h ----
        {
            float* qS = s_scores;                 // [32][68]
            float* wT = s_scores + 32 * 68;       // [64][68], [k][j]
            const int r8 = tid >> 3, cb = tid & 7;
            float acc8[8];
            #pragma unroll
            for (int j = 0; j < 8; j++) acc8[j] = 0.0f;

            for (int e0 = 0; e0 < 1024; e0 += 64) {
                __syncthreads();
                for (int i = tid; i < 32 * 16; i += 256) {
                    const int r = i >> 4, c4 = i & 15;
                    *(float4*)&qS[r * 68 + c4 * 4] =
                        *(const float4*)&query[((size_t)(b * SS) + q0 + r) * 1024 + e0 + c4 * 4];
                }
                for (int i = tid; i < 64 * 16; i += 256) {
                    const int j = i >> 4, c4 = i & 15;
                    float4 w = *(const float4*)&in_w[(size_t)(h * 64 + j) * 1024 + e0 + c4 * 4];
                    wT[(c4*4+0) * 68 + j] = w.x;
                    wT[(c4*4+1) * 68 + j] = w.y;
                    wT[(c4*4+2) * 68 + j] = w.z;
                    wT[(c4*4+3) * 68 + j] = w.w;
                }
                __syncthreads();

                #pragma unroll 8
                for (int kk = 0; kk < 64; kk++) {
                    const float qv = qS[r8 * 68 + kk];
                    const float4 w0 = *(const float4*)&wT[kk * 68 + cb * 8];
                    const float4 w1 = *(const float4*)&wT[kk * 68 + cb * 8 + 4];
                    acc8[0] = fmaf(qv, w0.x, acc8[0]);
                    acc8[1] = fmaf(qv, w0.y, acc8[1]);
                    acc8[2] = fmaf(qv, w0.z, acc8[2]);
                    acc8[3] = fmaf(qv, w0.w, acc8[3]);
                    acc8[4] = fmaf(qv, w1.x, acc8[4]);
                    acc8[5] = fmaf(qv, w1.y, acc8[5]);
                    acc8[6] = fmaf(qv, w1.z, acc8[6]);
                    acc8[7] = fmaf(qv, w1.w, acc8[7]);
                }
            }
            __syncthreads();
            #pragma unroll
            for (int j = 0; j < 8; j++) {
                const int col = cb * 8 + j;
                s_q[r8 * 68 + col] = acc8[j] + in_b[h * 64 + col];
            }
        }

        // ---- scores ----
        for (int kt = 0; kt < 16; kt++) {
            __syncthreads();
            for (int i = tid; i < 64 * 32; i += 256) {
                const int r = i >> 5, c2 = i & 31;
                const __half2 hv = *(const __half2*)&Kb[(size_t)(kt * 64 + r) * DD + c2 * 2];
                const float2 fv = __half22float2(hv);
                s_kv[r * 68 + c2 * 2]     = fv.x;
                s_kv[r * 68 + c2 * 2 + 1] = fv.y;
            }
            __syncthreads();

            float acc[8];
            #pragma unroll
            for (int j = 0; j < 8; j++) acc[j] = 0.0f;

            #pragma unroll
            for (int d4 = 0; d4 < 16; d4++) {
                const float4 kvv = *(const float4*)&s_kv[kj * 68 + d4 * 4];
                #pragma unroll
                for (int j = 0; j < 8; j++) {
                    const int qi = qb + j * 4;
                    const float4 qv = *(const float4*)&s_q[qi * 68 + d4 * 4];
                    acc[j] = fmaf(qv.x, kvv.x, acc[j]);
                    acc[j] = fmaf(qv.y, kvv.y, acc[j]);
                    acc[j] = fmaf(qv.z, kvv.z, acc[j]);
                    acc[j] = fmaf(qv.w, kvv.w, acc[j]);
                }
            }

            const int kg = kt * 64 + kj;
            const float keep = s_keep[kg];
            #pragma unroll
            for (int j = 0; j < 8; j++) {
                const int qi = qb + j * 4;
                float sc = acc[j] * SCALE + (float)(q0 + qi - kg);
                sc = (keep != 0.0f) ? sc : neg_inf();
                s_scores[qi * 1024 + kg] = sc;
            }
        }
        __syncthreads();

        // ---- softmax + direct mean write/accumulate ----
        {
            float* srow = s_scores + row * 1024;

            float mx = neg_inf();
            for (int c = lane; c < 1024; c += 8) mx = fmaxf(mx, srow[c]);
            #pragma unroll
            for (int m = 1; m < 8; m <<= 1)
                mx = fmaxf(mx, __shfl_xor_sync(0xffffffffu, mx, m, 8));

            float sum = 0.0f;
            for (int c = lane; c < 1024; c += 8) {
                const float p = __expf(srow[c] - mx);
                srow[c] = p;
                sum += p;
            }
            #pragma unroll
            for (int m = 1; m < 8; m <<= 1)
                sum += __shfl_xor_sync(0xffffffffu, sum, m, 8);

            const float inv = 1.0f / sum;
            float* mrow = mean_out + ((size_t)(b * SS) + q0 + row) * SS;
            if (h == 0) {
                for (int c = lane; c < 1024; c += 8) {
                    const float p = srow[c] * inv;
                    srow[c] = p;
                    mrow[c] = p * 0.0625f;
                }
            } else {
                for (int c = lane; c < 1024; c += 8) {
                    const float p = srow[c] * inv;
                    srow[c] = p;
                    mrow[c] += p * 0.0625f;
                }
            }
        }

        // ---- ctx tile = P @ V -> smem fp16 (cols h*64 .. h*64+63) ----
        {
            const int d = tid & 63;
            float cacc[8];
            #pragma unroll
            for (int j = 0; j < 8; j++) cacc[j] = 0.0f;

            for (int kt = 0; kt < 16; kt++) {
                __syncthreads();
                for (int i = tid; i < 64 * 32; i += 256) {
                    const int r = i >> 5, c2 = i & 31;
                    const __half2 hv = *(const __half2*)&Vb[(size_t)(kt * 64 + r) * DD + c2 * 2];
                    const float2 fv = __half22float2(hv);
                    s_kv[r * 68 + c2 * 2]     = fv.x;
                    s_kv[r * 68 + c2 * 2 + 1] = fv.y;
                }
                __syncthreads();

                #pragma unroll 4
                for (int kk = 0; kk < 64; kk++) {
                    const float v = s_kv[kk * 68 + d];
                    const int kg = kt * 64 + kk;
                    #pragma unroll
                    for (int j = 0; j < 8; j++) {
                        const int qi = qb + j * 4;
                        cacc[j] = fmaf(s_scores[qi * 1024 + kg], v, cacc[j]);
                    }
                }
            }

            #pragma unroll
            for (int j = 0; j < 8; j++) {
                const int qi = qb + j * 4;
                s_ctx[qi * 1024 + h * 64 + d] = __float2half(cacc[j]);
            }
        }
        __syncthreads();
    }

    // ==================== grid barrier ====================
    // All 128 blocks co-resident (1 block/SM). Monotonic counter: target is
    // the next multiple of NBLK, so replays need no reset.
    if (tid == 0) {
        __threadfence();
        const unsigned int old = atomicAdd(&g_bar, 1u);
        const unsigned int target = (old / NBLK + 1u) * NBLK;
        while (atomicAdd(&g_bar, 0u) < target) { }
    }
    __syncthreads();

    // ==================== Phase B: out tile = ctx @ Wo^T + bias ====================
    {
        const int r2 = tid >> 4;     // rows r2*2, r2*2+1
        const int c16 = tid & 15;    // cols c16*4 .. +3
        float* wS = s_scores;        // staging [256][68] (scores dead)

        for (int n0 = 0; n0 < 1024; n0 += 64) {
            float acc[2][4];
            #pragma unroll
            for (int i = 0; i < 2; i++)
                #pragma unroll
                for (int j = 0; j < 4; j++) acc[i][j] = 0.0f;

            for (int k0 = 0; k0 < 1024; k0 += 256) {
                __syncthreads();
                for (int i = tid; i < 64 * 64; i += 256) {
                    const int nn = i >> 6;
                    const int k4 = i & 63;
                    float4 w = *(const float4*)&out_w[(size_t)(n0 + nn) * 1024 + k0 + k4 * 4];
                    wS[(k4*4+0) * 68 + nn] = w.x;
                    wS[(k4*4+1) * 68 + nn] = w.y;
                    wS[(k4*4+2) * 68 + nn] = w.z;
                    wS[(k4*4+3) * 68 + nn] = w.w;
                }
                __syncthreads();

                #pragma unroll 4
                for (int kk = 0; kk < 256; kk++) {
                    const float a0 = __half2float(s_ctx[(r2*2 + 0) * 1024 + k0 + kk]);
                    const float a1 = __half2float(s_ctx[(r2*2 + 1) * 1024 + k0 + kk]);
                    const float4 wv = *(const float4*)&wS[kk * 68 + c16 * 4];
                    acc[0][0] = fmaf(a0, wv.x, acc[0][0]);
                    acc[0][1] = fmaf(a0, wv.y, acc[0][1]);
                    acc[0][2] = fmaf(a0, wv.z, acc[0][2]);
                    acc[0][3] = fmaf(a0, wv.w, acc[0][3]);
                    acc[1][0] = fmaf(a1, wv.x, acc[1][0]);
                    acc[1][1] = fmaf(a1, wv.y, acc[1][1]);
                    acc[1][2] = fmaf(a1, wv.z, acc[1][2]);
                    acc[1][3] = fmaf(a1, wv.w, acc[1][3]);
                }
            }

            #pragma unroll
            for (int i = 0; i < 2; i++) {
                const int r = r2 * 2 + i;
                #pragma unroll
                for (int j = 0; j < 4; j++) {
                    const int n = n0 + c16 * 4 + j;
                    out[((size_t)(b * SS) + q0 + r) * 1024 + n] = acc[i][j] + out_b[n];
                }
            }
        }
    }
}

// ============================================================================
extern "C" void kernel_launch(void* const* d_in, const int* in_sizes, int n_in,
                              void* d_out, int out_size)
{
    const float* query = (const float*)d_in[0];
    const float* key   = (const float*)d_in[1];
    const float* value = (const float*)d_in[2];
    const unsigned int* mask_w = (const unsigned int*)d_in[3];  // bool promoted to i32/f32
    const float* in_w  = (const float*)d_in[4];
    const float* in_b  = (const float*)d_in[5];
    const float* out_w = (const float*)d_in[6];
    const float* out_b = (const float*)d_in[7];

    float* out      = (float*)d_out;                 // (B,S,E); holds kv fp16 until phase B
    float* mean_out = out + (size_t)BB * SS * EE;    // (B,S,S)
    __half* kv      = (__half*)d_out;                // K at [0], V at [+4M halves]

    cudaFuncSetAttribute(fused_attn_kernel,
                         cudaFuncAttributeMaxDynamicSharedMemorySize, FUSED_SMEM);

    // 1. K/V projection -> fp16 into the (dead) output region
    kv_proj_kernel<<<dim3(32, HH, BB), 256>>>(key, value, in_w, in_b, kv);

    // 2. fused attention + out-projection (writes mean directly, then output)
    fused_attn_kernel<<<dim3(SS / NQ, BB), 256, FUSED_SMEM>>>(
        query, in_w, in_b, mask_w, kv, out_w, out_b, mean_out, out);
}

// round 9
// speedup vs baseline: 1.0688x; 1.0675x over previous
#include <cuda_runtime.h>
#include <cuda_fp16.h>

#define BB 4
#define SS 1024
#define EE 1024
#define HH 16
#define DD 64
#define NQ 32
#define SCALE 0.125f
#define NBLK (BB * (SS / NQ))   // 128 fused blocks

__device__ unsigned int g_bar;  // monotonic grid barrier (no reset needed)

__device__ __forceinline__ float neg_inf() { return __int_as_float(0xff800000); }

// fused smem layout (bytes), total 226816 <= 227KB:
//   s_scores : 32*1024 f32 = 131072   (also qS/wT and Wo staging)
//   s_ctx    : 32*1024 f16 =  65536
//   s_k      : 64*65   f32 =  16640 (+pad to 17408)  K/V tile, stride 65
//   s_q      : 32*68   f32 =   8704
//   s_keep   : 1024    f32 =   4096
#define SM_CTX   131072
#define SM_K     (131072 + 65536)
#define SM_Q     (SM_K + 17408)
#define SM_KEEP  (SM_Q + 8704)
#define FUSED_SMEM (SM_KEEP + 4096)

// ============================================================================
// P1: K/V projection -> fp16 into the (currently dead) output region.
// ============================================================================
__global__ void kv_proj_kernel(const float* __restrict__ key,
                               const float* __restrict__ value,
                               const float* __restrict__ in_w,
                               const float* __restrict__ in_b,
                               __half* __restrict__ kv)
{
    __shared__ float As[16][68];
    __shared__ float Bs[16][68];

    const int which = blockIdx.x >> 4;            // 0=k, 1=v
    const int s0 = (blockIdx.x & 15) * 64;
    const int h = blockIdx.y, b = blockIdx.z;
    const float* X = (which ? value : key) + (size_t)b * SS * EE;
    const int woff = (which ? 2048 : 1024) + h * 64;

    const int tid = threadIdx.x;
    const int tx = tid & 15, ty = tid >> 4;
    const int lr = tid >> 2, lc = tid & 3;

    float acc[4][4];
    #pragma unroll
    for (int i = 0; i < 4; i++)
        #pragma unroll
        for (int j = 0; j < 4; j++) acc[i][j] = 0.0f;

    for (int k0 = 0; k0 < 1024; k0 += 16) {
        float4 a = *(const float4*)&X[(size_t)(s0 + lr) * 1024 + k0 + lc * 4];
        float4 w = *(const float4*)&in_w[(size_t)(woff + lr) * 1024 + k0 + lc * 4];
        As[lc*4+0][lr] = a.x; As[lc*4+1][lr] = a.y;
        As[lc*4+2][lr] = a.z; As[lc*4+3][lr] = a.w;
        Bs[lc*4+0][lr] = w.x; Bs[lc*4+1][lr] = w.y;
        Bs[lc*4+2][lr] = w.z; Bs[lc*4+3][lr] = w.w;
        __syncthreads();

        #pragma unroll
        for (int kk = 0; kk < 16; kk++) {
            float4 ra = *(const float4*)&As[kk][ty * 4];
            float4 rb = *(const float4*)&Bs[kk][tx * 4];
            float va[4] = {ra.x, ra.y, ra.z, ra.w};
            float vb[4] = {rb.x, rb.y, rb.z, rb.w};
            #pragma unroll
            for (int i = 0; i < 4; i++)
                #pragma unroll
                for (int j = 0; j < 4; j++)
                    acc[i][j] = fmaf(va[i], vb[j], acc[i][j]);
        }
        __syncthreads();
    }

    __half* dst = kv + (size_t)which * (BB*HH*SS*DD)
                     + ((size_t)(b * HH + h) * SS) * DD;
    #pragma unroll
    for (int i = 0; i < 4; i++) {
        const int s = s0 + ty * 4 + i;
        #pragma unroll
        for (int j = 0; j < 4; j++) {
            const int d = tx * 4 + j;
            dst[(size_t)s * DD + d] = __float2half(acc[i][j] + in_b[woff + d]);
        }
    }
}

// ============================================================================
// P2: fused attention + output projection. grid (32 qt, 4 b), 512 threads.
// ============================================================================
__global__ void __launch_bounds__(512, 1)
fused_attn_kernel(const float* __restrict__ query,
                  const float* __restrict__ in_w,
                  const float* __restrict__ in_b,
                  const unsigned int* __restrict__ mask_w,
                  const __half* __restrict__ kv,
                  const float* __restrict__ out_w,
                  const float* __restrict__ out_b,
                  float* __restrict__ mean_out,
                  float* __restrict__ out)
{
    extern __shared__ char smem[];
    float*  s_scores = (float*)smem;
    __half* s_ctx    = (__half*)(smem + SM_CTX);
    float*  s_k      = (float*)(smem + SM_K);      // [64][65] K or V tile
    float*  s_q      = (float*)(smem + SM_Q);      // [32][68]
    float*  s_keep   = (float*)(smem + SM_KEEP);   // [1024]

    const int qt = blockIdx.x, b = blockIdx.y;
    const int q0 = qt * NQ;
    const int tid = threadIdx.x;

    for (int i = tid; i < 1024; i += 512)
        s_keep[i] = (mask_w[b * SS + i] != 0u) ? 1.0f : 0.0f;

    const int kj = tid & 63;        // k index within 64-tile (scores) / d (pv)
    const int qb = tid >> 6;        // 0..7, qi = qb + 8*j
    const int wid = tid >> 5;       // warp id 0..15
    const int lid = tid & 31;

    // ==================== Phase A: heads loop ====================
    for (int h = 0; h < HH; h++) {
        const __half* Kb = kv + ((size_t)(b * HH + h) * SS) * DD;
        const __half* Vb = Kb + (size_t)(BB*HH*SS*DD);

        // ---- q tile = query[b, q0:q0+32, :] @ wq_h^T + bq_h ----
        {
            float* qS = s_scores;                 // [32][68]
            float* wT = s_scores + 32 * 68;       // [64 kk][68 j]
            const int r = tid >> 4;               // 0..31
            const int cb = tid & 15;              // 0..15 -> cols cb*4..+3
            float acc4[4] = {0.0f, 0.0f, 0.0f, 0.0f};

            for (int e0 = 0; e0 < 1024; e0 += 64) {
                __syncthreads();
                {   // stage query chunk: 512 float4, one per thread
                    const int rr = tid >> 4, c4 = tid & 15;
                    *(float4*)&qS[rr * 68 + c4 * 4] =
                        *(const float4*)&query[((size_t)(b * SS) + q0 + rr) * 1024 + e0 + c4 * 4];
                }
                #pragma unroll
                for (int i = tid; i < 1024; i += 512) {  // wT: 1024 float4
                    const int j = i >> 4, k4 = i & 15;
                    float4 w = *(const float4*)&in_w[(size_t)(h * 64 + j) * 1024 + e0 + k4 * 4];
                    wT[(k4*4+0) * 68 + j] = w.x;
                    wT[(k4*4+1) * 68 + j] = w.y;
                    wT[(k4*4+2) * 68 + j] = w.z;
                    wT[(k4*4+3) * 68 + j] = w.w;
                }
                __syncthreads();

                #pragma unroll 8
                for (int kk = 0; kk < 64; kk++) {
                    const float qv = qS[r * 68 + kk];
                    const float4 w4 = *(const float4*)&wT[kk * 68 + cb * 4];
                    acc4[0] = fmaf(qv, w4.x, acc4[0]);
                    acc4[1] = fmaf(qv, w4.y, acc4[1]);
                    acc4[2] = fmaf(qv, w4.z, acc4[2]);
                    acc4[3] = fmaf(qv, w4.w, acc4[3]);
                }
            }
            __syncthreads();
            #pragma unroll
            for (int c = 0; c < 4; c++)
                s_q[r * 68 + cb * 4 + c] = acc4[c] + in_b[h * 64 + cb * 4 + c];
        }

        // ---- scores: K tile staged at stride 65 (conflict-free scalar reads) ----
        for (int kt = 0; kt < 16; kt++) {
            __syncthreads();
            for (int i = tid; i < 64 * 32; i += 512) {
                const int r = i >> 5, c2 = i & 31;
                const float2 fv = __half22float2(
                    *(const __half2*)&Kb[(size_t)(kt * 64 + r) * DD + c2 * 2]);
                s_k[r * 65 + c2 * 2]     = fv.x;
                s_k[r * 65 + c2 * 2 + 1] = fv.y;
            }
            __syncthreads();

            float acc[4] = {0.0f, 0.0f, 0.0f, 0.0f};
            #pragma unroll
            for (int d4 = 0; d4 < 16; d4++) {
                const float k0v = s_k[kj * 65 + d4 * 4 + 0];
                const float k1v = s_k[kj * 65 + d4 * 4 + 1];
                const float k2v = s_k[kj * 65 + d4 * 4 + 2];
                const float k3v = s_k[kj * 65 + d4 * 4 + 3];
                #pragma unroll
                for (int j = 0; j < 4; j++) {
                    const float4 qv = *(const float4*)&s_q[(qb + 8*j) * 68 + d4 * 4];
                    acc[j] = fmaf(qv.x, k0v, acc[j]);
                    acc[j] = fmaf(qv.y, k1v, acc[j]);
                    acc[j] = fmaf(qv.z, k2v, acc[j]);
                    acc[j] = fmaf(qv.w, k3v, acc[j]);
                }
            }

            const int kg = kt * 64 + kj;
            const float keep = s_keep[kg];
            #pragma unroll
            for (int j = 0; j < 4; j++) {
                const int qi = qb + 8*j;
                float sc = acc[j] * SCALE + (float)(q0 + qi - kg);
                sc = (keep != 0.0f) ? sc : neg_inf();
                s_scores[qi * 1024 + kg] = sc;
            }
        }
        __syncthreads();

        // ---- softmax: warp per row (2 rows/warp), conflict-free ----
        for (int r = wid; r < 32; r += 16) {
            float* srow = s_scores + r * 1024;

            float mx = neg_inf();
            #pragma unroll 4
            for (int c = lid; c < 1024; c += 32) mx = fmaxf(mx, srow[c]);
            #pragma unroll
            for (int m = 16; m >= 1; m >>= 1)
                mx = fmaxf(mx, __shfl_xor_sync(0xffffffffu, mx, m));

            float sum = 0.0f;
            #pragma unroll 4
            for (int c = lid; c < 1024; c += 32) {
                const float p = __expf(srow[c] - mx);
                srow[c] = p;
                sum += p;
            }
            #pragma unroll
            for (int m = 16; m >= 1; m >>= 1)
                sum += __shfl_xor_sync(0xffffffffu, sum, m);

            const float inv = 1.0f / sum;
            float* mrow = mean_out + ((size_t)(b * SS) + q0 + r) * SS;
            if (h == 0) {
                #pragma unroll 4
                for (int c = lid; c < 1024; c += 32) {
                    const float p = srow[c] * inv;
                    srow[c] = p;
                    mrow[c] = p * 0.0625f;
                }
            } else {
                #pragma unroll 4
                for (int c = lid; c < 1024; c += 32) {
                    const float p = srow[c] * inv;
                    srow[c] = p;
                    mrow[c] += p * 0.0625f;
                }
            }
        }

        // ---- ctx tile = P @ V -> smem fp16 ----
        {
            const int d = kj;                 // 0..63
            float cacc[4] = {0.0f, 0.0f, 0.0f, 0.0f};

            for (int kt = 0; kt < 16; kt++) {
                __syncthreads();
                for (int i = tid; i < 64 * 32; i += 512) {
                    const int r = i >> 5, c2 = i & 31;
                    const float2 fv = __half22float2(
                        *(const __half2*)&Vb[(size_t)(kt * 64 + r) * DD + c2 * 2]);
                    s_k[r * 65 + c2 * 2]     = fv.x;
                    s_k[r * 65 + c2 * 2 + 1] = fv.y;
                }
                __syncthreads();

                #pragma unroll 8
                for (int kk = 0; kk < 64; kk++) {
                    const float v = s_k[kk * 65 + d];
                    const int kg = kt * 64 + kk;
                    #pragma unroll
                    for (int j = 0; j < 4; j++)
                        cacc[j] = fmaf(s_scores[(qb + 8*j) * 1024 + kg], v, cacc[j]);
                }
            }

            #pragma unroll
            for (int j = 0; j < 4; j++)
                s_ctx[(qb + 8*j) * 1024 + h * 64 + d] = __float2half(cacc[j]);
        }
        __syncthreads();
    }

    // ==================== grid barrier ====================
    if (tid == 0) {
        __threadfence();
        const unsigned int old = atomicAdd(&g_bar, 1u);
        const unsigned int target = (old / NBLK + 1u) * NBLK;
        while (atomicAdd(&g_bar, 0u) < target) { }
    }
    __syncthreads();

    // ==================== Phase B: out = ctx @ Wo^T + bias ====================
    {
        const int r  = tid >> 4;     // 0..31
        const int c16 = tid & 15;    // cols c16*4..+3
        float* wS = s_scores;        // [256 kk][68 n] staging (scores dead)

        for (int n0 = 0; n0 < 1024; n0 += 64) {
            float acc[4] = {0.0f, 0.0f, 0.0f, 0.0f};

            for (int k0 = 0; k0 < 1024; k0 += 256) {
                __syncthreads();
                #pragma unroll
                for (int i = tid; i < 64 * 64; i += 512) {
                    const int nn = i >> 6;
                    const int k4 = i & 63;
                    float4 w = *(const float4*)&out_w[(size_t)(n0 + nn) * 1024 + k0 + k4 * 4];
                    wS[(k4*4+0) * 68 + nn] = w.x;
                    wS[(k4*4+1) * 68 + nn] = w.y;
                    wS[(k4*4+2) * 68 + nn] = w.z;
                    wS[(k4*4+3) * 68 + nn] = w.w;
                }
                __syncthreads();

                #pragma unroll 8
                for (int kk = 0; kk < 256; kk++) {
                    const float a = __half2float(s_ctx[r * 1024 + k0 + kk]);
                    const float4 wv = *(const float4*)&wS[kk * 68 + c16 * 4];
                    acc[0] = fmaf(a, wv.x, acc[0]);
                    acc[1] = fmaf(a, wv.y, acc[1]);
                    acc[2] = fmaf(a, wv.z, acc[2]);
                    acc[3] = fmaf(a, wv.w, acc[3]);
                }
            }

            #pragma unroll
            for (int j = 0; j < 4; j++) {
                const int n = n0 + c16 * 4 + j;
                out[((size_t)(b * SS) + q0 + r) * 1024 + n] = acc[j] + out_b[n];
            }
        }
    }
}

// ============================================================================
extern "C" void kernel_launch(void* const* d_in, const int* in_sizes, int n_in,
                              void* d_out, int out_size)
{
    const float* query = (const float*)d_in[0];
    const float* key   = (const float*)d_in[1];
    const float* value = (const float*)d_in[2];
    const unsigned int* mask_w = (const unsigned int*)d_in[3];
    const float* in_w  = (const float*)d_in[4];
    const float* in_b  = (const float*)d_in[5];
    const float* out_w = (const float*)d_in[6];
    const float* out_b = (const float*)d_in[7];

    float* out      = (float*)d_out;                 // (B,S,E); kv fp16 until phase B
    float* mean_out = out + (size_t)BB * SS * EE;    // (B,S,S)
    __half* kv      = (__half*)d_out;

    cudaFuncSetAttribute(fused_attn_kernel,
                         cudaFuncAttributeMaxDynamicSharedMemorySize, FUSED_SMEM);

    kv_proj_kernel<<<dim3(32, HH, BB), 256>>>(key, value, in_w, in_b, kv);

    fused_attn_kernel<<<dim3(SS / NQ, BB), 512, FUSED_SMEM>>>(
        query, in_w, in_b, mask_w, kv, out_w, out_b, mean_out, out);
}

// round 10
// speedup vs baseline: 2.8544x; 2.6705x over previous
#include <cuda_runtime.h>
#include <cuda_fp16.h>

#define BB 4
#define SS 1024
#define EE 1024
#define HH 16
#define DD 64
#define NQ 32
#define SCALE 0.125f
#define NBLK (BB * (SS / NQ))   // 128 fused blocks
#define NEGINF __int_as_float(0xff800000)

__device__ unsigned int g_bar;  // monotonic grid barrier (no reset needed)

// fused smem layout (bytes):
//   s_scores f32 [32][1032] = 132096   (also qproj staging / Wo fp16 staging / P~ fp16)
//   s_ctx    f16 [32][1032] =  66048
//   s_kt     f16 [64][72]   =   9216   (K tile or V^T tile)
//   s_q16    f16 [32][72]   =   4608
//   s_keep   f32 [1024]     =   4096
//   s_inv    f32 [32]       =    128
#define SMB_CTX    132096
#define SMB_KT     (SMB_CTX + 66048)
#define SMB_Q16    (SMB_KT + 9216)
#define SMB_KEEP   (SMB_Q16 + 4608)
#define SMB_INV    (SMB_KEEP + 4096)
#define FUSED_SMEM (SMB_INV + 128)      // 216192 <= 227KB

// m16n8k16 row.col f32.f16.f16.f32
__device__ __forceinline__ void mma16816(float c[4], const unsigned a[4],
                                         const unsigned bf[2]) {
    asm volatile(
        "mma.sync.aligned.m16n8k16.row.col.f32.f16.f16.f32 "
        "{%0,%1,%2,%3}, {%4,%5,%6,%7}, {%8,%9}, {%0,%1,%2,%3};\n"
        : "+f"(c[0]), "+f"(c[1]), "+f"(c[2]), "+f"(c[3])
        : "r"(a[0]), "r"(a[1]), "r"(a[2]), "r"(a[3]), "r"(bf[0]), "r"(bf[1]));
}

// ============================================================================
// P1: K/V projection -> fp16 into the (currently dead) output region.
// ============================================================================
__global__ void kv_proj_kernel(const float* __restrict__ key,
                               const float* __restrict__ value,
                               const float* __restrict__ in_w,
                               const float* __restrict__ in_b,
                               __half* __restrict__ kv)
{
    __shared__ float As[16][68];
    __shared__ float Bs[16][68];

    const int which = blockIdx.x >> 4;            // 0=k, 1=v
    const int s0 = (blockIdx.x & 15) * 64;
    const int h = blockIdx.y, b = blockIdx.z;
    const float* X = (which ? value : key) + (size_t)b * SS * EE;
    const int woff = (which ? 2048 : 1024) + h * 64;

    const int tid = threadIdx.x;
    const int tx = tid & 15, ty = tid >> 4;
    const int lr = tid >> 2, lc = tid & 3;

    float acc[4][4];
    #pragma unroll
    for (int i = 0; i < 4; i++)
        #pragma unroll
        for (int j = 0; j < 4; j++) acc[i][j] = 0.0f;

    for (int k0 = 0; k0 < 1024; k0 += 16) {
        float4 a = *(const float4*)&X[(size_t)(s0 + lr) * 1024 + k0 + lc * 4];
        float4 w = *(const float4*)&in_w[(size_t)(woff + lr) * 1024 + k0 + lc * 4];
        As[lc*4+0][lr] = a.x; As[lc*4+1][lr] = a.y;
        As[lc*4+2][lr] = a.z; As[lc*4+3][lr] = a.w;
        Bs[lc*4+0][lr] = w.x; Bs[lc*4+1][lr] = w.y;
        Bs[lc*4+2][lr] = w.z; Bs[lc*4+3][lr] = w.w;
        __syncthreads();

        #pragma unroll
        for (int kk = 0; kk < 16; kk++) {
            float4 ra = *(const float4*)&As[kk][ty * 4];
            float4 rb = *(const float4*)&Bs[kk][tx * 4];
            float va[4] = {ra.x, ra.y, ra.z, ra.w};
            float vb[4] = {rb.x, rb.y, rb.z, rb.w};
            #pragma unroll
            for (int i = 0; i < 4; i++)
                #pragma unroll
                for (int j = 0; j < 4; j++)
                    acc[i][j] = fmaf(va[i], vb[j], acc[i][j]);
        }
        __syncthreads();
    }

    __half* dst = kv + (size_t)which * (BB*HH*SS*DD)
                     + ((size_t)(b * HH + h) * SS) * DD;
    #pragma unroll
    for (int i = 0; i < 4; i++) {
        const int s = s0 + ty * 4 + i;
        #pragma unroll
        for (int j = 0; j < 4; j++) {
            const int d = tx * 4 + j;
            dst[(size_t)s * DD + d] = __float2half(acc[i][j] + in_b[woff + d]);
        }
    }
}

// ============================================================================
// P2: fused attention + out-projection, tensor-core edition. 512 threads.
// ============================================================================
__global__ void __launch_bounds__(512, 1)
fused_attn_kernel(const float* __restrict__ query,
                  const float* __restrict__ in_w,
                  const float* __restrict__ in_b,
                  const unsigned int* __restrict__ mask_w,
                  const __half* __restrict__ kv,
                  const float* __restrict__ out_w,
                  const float* __restrict__ out_b,
                  float* __restrict__ mean_out,
                  float* __restrict__ out)
{
    extern __shared__ char smem[];
    float*  s_scores = (float*)smem;                 // [32][1032] f32
    __half* s_ctx    = (__half*)(smem + SMB_CTX);    // [32][1032] f16
    __half* s_kt     = (__half*)(smem + SMB_KT);     // [64][72] f16
    __half* s_q16    = (__half*)(smem + SMB_Q16);    // [32][72] f16
    float*  s_keep   = (float*)(smem + SMB_KEEP);
    float*  s_inv    = (float*)(smem + SMB_INV);

    const int qt = blockIdx.x, b = blockIdx.y;
    const int q0 = qt * NQ;
    const int tid = threadIdx.x;
    const int wid = tid >> 5, lane = tid & 31;
    const int g = lane >> 2, t = lane & 3;
    const int mw = (wid >> 3) * 16;   // warp m-tile base (0|16)
    const int nw = (wid & 7) * 8;     // warp n-subtile base (0..56)

    for (int i = tid; i < 1024; i += 512)
        s_keep[i] = (mask_w[b * SS + i] != 0u) ? 1.0f : 0.0f;

    for (int h = 0; h < HH; h++) {
        const __half* Kb = kv + ((size_t)(b * HH + h) * SS) * DD;
        const __half* Vb = Kb + (size_t)(BB*HH*SS*DD);

        // ---------- Q-proj (mma): q16 = fp16(query) @ fp16(wq_h)^T + b ----------
        {
            __half* qst = (__half*)smem;          // [32][264]
            __half* wst = qst + 32 * 264;         // [64][264]
            float qc[4] = {0.f, 0.f, 0.f, 0.f};

            for (int e0 = 0; e0 < 1024; e0 += 256) {
                __syncthreads();
                for (int i = tid; i < 2048; i += 512) {
                    const int r = i >> 6, c4 = i & 63;
                    float4 v = *(const float4*)&query[((size_t)(b*SS)+q0+r)*1024 + e0 + c4*4];
                    *(__half2*)&qst[r*264 + c4*4]     = __floats2half2_rn(v.x, v.y);
                    *(__half2*)&qst[r*264 + c4*4 + 2] = __floats2half2_rn(v.z, v.w);
                }
                for (int i = tid; i < 4096; i += 512) {
                    const int r = i >> 6, c4 = i & 63;
                    float4 v = *(const float4*)&in_w[(size_t)(h*64+r)*1024 + e0 + c4*4];
                    *(__half2*)&wst[r*264 + c4*4]     = __floats2half2_rn(v.x, v.y);
                    *(__half2*)&wst[r*264 + c4*4 + 2] = __floats2half2_rn(v.z, v.w);
                }
                __syncthreads();

                #pragma unroll
                for (int ks = 0; ks < 16; ks++) {
                    const int k0 = ks * 16;
                    unsigned a[4], bf[2];
                    a[0] = *(const unsigned*)&qst[(mw+g)*264 + k0 + t*2];
                    a[1] = *(const unsigned*)&qst[(mw+g+8)*264 + k0 + t*2];
                    a[2] = *(const unsigned*)&qst[(mw+g)*264 + k0 + t*2 + 8];
                    a[3] = *(const unsigned*)&qst[(mw+g+8)*264 + k0 + t*2 + 8];
                    bf[0] = *(const unsigned*)&wst[(nw+g)*264 + k0 + t*2];
                    bf[1] = *(const unsigned*)&wst[(nw+g)*264 + k0 + t*2 + 8];
                    mma16816(qc, a, bf);
                }
            }
            const float bb0 = in_b[h*64 + nw + t*2];
            const float bb1 = in_b[h*64 + nw + t*2 + 1];
            *(__half2*)&s_q16[(mw+g)*72 + nw + t*2]   = __floats2half2_rn(qc[0]+bb0, qc[1]+bb1);
            *(__half2*)&s_q16[(mw+g+8)*72 + nw + t*2] = __floats2half2_rn(qc[2]+bb0, qc[3]+bb1);
        }
        __syncthreads();

        // hoisted A-frags (Q) for scores: same for all kt
        unsigned aq[4][4];
        #pragma unroll
        for (int ks = 0; ks < 4; ks++) {
            const int k0 = ks * 16;
            aq[ks][0] = *(const unsigned*)&s_q16[(mw+g)*72 + k0 + t*2];
            aq[ks][1] = *(const unsigned*)&s_q16[(mw+g+8)*72 + k0 + t*2];
            aq[ks][2] = *(const unsigned*)&s_q16[(mw+g)*72 + k0 + t*2 + 8];
            aq[ks][3] = *(const unsigned*)&s_q16[(mw+g+8)*72 + k0 + t*2 + 8];
        }

        // ---------- scores (mma) ----------
        for (int kt = 0; kt < 16; kt++) {
            for (int i = tid; i < 1024; i += 512) {      // K tile straight fp16 copy
                const int r = i >> 4, c8 = i & 15;
                *(uint2*)&s_kt[r*72 + c8*4] =
                    *(const uint2*)&Kb[(size_t)(kt*64 + r)*64 + c8*4];
            }
            __syncthreads();

            float sc4[4] = {0.f, 0.f, 0.f, 0.f};
            #pragma unroll
            for (int ks = 0; ks < 4; ks++) {
                const int k0 = ks * 16;
                unsigned bf[2];
                bf[0] = *(const unsigned*)&s_kt[(nw+g)*72 + k0 + t*2];
                bf[1] = *(const unsigned*)&s_kt[(nw+g)*72 + k0 + t*2 + 8];
                mma16816(sc4, aq[ks], bf);
            }

            const int kg = kt*64 + nw + t*2;
            const float kf0 = s_keep[kg], kf1 = s_keep[kg+1];
            const int r0 = mw + g, r1 = mw + g + 8;
            float v00 = sc4[0]*SCALE + (float)(q0 + r0 - kg);
            float v01 = sc4[1]*SCALE + (float)(q0 + r0 - kg - 1);
            float v10 = sc4[2]*SCALE + (float)(q0 + r1 - kg);
            float v11 = sc4[3]*SCALE + (float)(q0 + r1 - kg - 1);
            v00 = (kf0 != 0.f) ? v00 : NEGINF;
            v01 = (kf1 != 0.f) ? v01 : NEGINF;
            v10 = (kf0 != 0.f) ? v10 : NEGINF;
            v11 = (kf1 != 0.f) ? v11 : NEGINF;
            *(float2*)&s_scores[r0*1032 + kg] = make_float2(v00, v01);
            *(float2*)&s_scores[r1*1032 + kg] = make_float2(v10, v11);
            __syncthreads();
        }

        // ---------- softmax (warp/row); P~ fp16 in place; mean from regs ----------
        for (int r = wid; r < 32; r += 16) {
            float* srow = s_scores + r * 1032;
            __half* prow = (__half*)srow;

            float mx = NEGINF;
            #pragma unroll
            for (int i = 0; i < 32; i++) mx = fmaxf(mx, srow[lane + 32*i]);
            #pragma unroll
            for (int m = 16; m >= 1; m >>= 1)
                mx = fmaxf(mx, __shfl_xor_sync(0xffffffffu, mx, m));

            float pv[32];
            float sum = 0.f;
            #pragma unroll
            for (int i = 0; i < 32; i++) {
                const float p = __expf(srow[lane + 32*i] - mx);
                pv[i] = p; sum += p;
            }
            #pragma unroll
            for (int m = 16; m >= 1; m >>= 1)
                sum += __shfl_xor_sync(0xffffffffu, sum, m);

            const float inv = 1.0f / sum;
            if (lane == 0) s_inv[r] = inv;

            #pragma unroll
            for (int i = 0; i < 32; i++)
                prow[lane + 32*i] = __float2half(pv[i]);

            float* mrow = mean_out + ((size_t)(b*SS) + q0 + r) * SS;
            const float msc = inv * 0.0625f;
            if (h == 0) {
                #pragma unroll
                for (int i = 0; i < 32; i++) mrow[lane + 32*i] = pv[i] * msc;
            } else {
                #pragma unroll
                for (int i = 0; i < 32; i++) mrow[lane + 32*i] += pv[i] * msc;
            }
        }
        __syncthreads();

        // ---------- PV (mma): ctx = (P~ @ V) * inv ----------
        {
            float cacc[4] = {0.f, 0.f, 0.f, 0.f};
            for (int kt = 0; kt < 16; kt++) {
                for (int i = tid; i < 1024; i += 512) {   // V^T tile
                    const int k = i >> 5, c2 = i & 31;
                    const __half2 hv = *(const __half2*)&Vb[(size_t)(kt*64 + k)*64 + c2*2];
                    s_kt[(c2*2)*72 + k]     = __low2half(hv);
                    s_kt[(c2*2 + 1)*72 + k] = __high2half(hv);
                }
                __syncthreads();

                #pragma unroll
                for (int ks = 0; ks < 4; ks++) {
                    const int kk = kt*64 + ks*16 + t*2;
                    unsigned a[4], bf[2];
                    a[0] = *(const unsigned*)((const char*)s_scores + (size_t)(mw+g)*4128 + kk*2);
                    a[1] = *(const unsigned*)((const char*)s_scores + (size_t)(mw+g+8)*4128 + kk*2);
                    a[2] = *(const unsigned*)((const char*)s_scores + (size_t)(mw+g)*4128 + (kk+8)*2);
                    a[3] = *(const unsigned*)((const char*)s_scores + (size_t)(mw+g+8)*4128 + (kk+8)*2);
                    bf[0] = *(const unsigned*)&s_kt[(nw+g)*72 + ks*16 + t*2];
                    bf[1] = *(const unsigned*)&s_kt[(nw+g)*72 + ks*16 + t*2 + 8];
                    mma16816(cacc, a, bf);
                }
                __syncthreads();
            }
            const int r0 = mw + g, r1 = mw + g + 8;
            const float i0 = s_inv[r0], i1 = s_inv[r1];
            *(__half2*)&s_ctx[r0*1032 + h*64 + nw + t*2] =
                __floats2half2_rn(cacc[0]*i0, cacc[1]*i0);
            *(__half2*)&s_ctx[r1*1032 + h*64 + nw + t*2] =
                __floats2half2_rn(cacc[2]*i1, cacc[3]*i1);
        }
        __syncthreads();
    }

    // ==================== grid barrier ====================
    if (tid == 0) {
        __threadfence();
        const unsigned int old = atomicAdd(&g_bar, 1u);
        const unsigned int target = (old / NBLK + 1u) * NBLK;
        while (atomicAdd(&g_bar, 0u) < target) { }
    }
    __syncthreads();

    // ==================== out-proj (mma): out = ctx @ Wo^T + bias ====================
    {
        __half* woS = (__half*)smem;              // [64][1032] fp16 (scores dead)
        for (int n0 = 0; n0 < 1024; n0 += 64) {
            __syncthreads();
            for (int i = tid; i < 16384; i += 512) {
                const int r = i >> 8, c4 = i & 255;
                float4 v = *(const float4*)&out_w[(size_t)(n0 + r)*1024 + c4*4];
                *(__half2*)&woS[r*1032 + c4*4]     = __floats2half2_rn(v.x, v.y);
                *(__half2*)&woS[r*1032 + c4*4 + 2] = __floats2half2_rn(v.z, v.w);
            }
            __syncthreads();

            float oc[4] = {0.f, 0.f, 0.f, 0.f};
            #pragma unroll 4
            for (int ks = 0; ks < 64; ks++) {
                const int k0 = ks * 16;
                unsigned a[4], bf[2];
                a[0] = *(const unsigned*)&s_ctx[(mw+g)*1032 + k0 + t*2];
                a[1] = *(const unsigned*)&s_ctx[(mw+g+8)*1032 + k0 + t*2];
                a[2] = *(const unsigned*)&s_ctx[(mw+g)*1032 + k0 + t*2 + 8];
                a[3] = *(const unsigned*)&s_ctx[(mw+g+8)*1032 + k0 + t*2 + 8];
                bf[0] = *(const unsigned*)&woS[(nw+g)*1032 + k0 + t*2];
                bf[1] = *(const unsigned*)&woS[(nw+g)*1032 + k0 + t*2 + 8];
                mma16816(oc, a, bf);
            }

            const int col = n0 + nw + t*2;
            const float bb0 = out_b[col], bb1 = out_b[col+1];
            const int r0 = mw + g, r1 = mw + g + 8;
            *(float2*)&out[((size_t)(b*SS)+q0+r0)*1024 + col] =
                make_float2(oc[0]+bb0, oc[1]+bb1);
            *(float2*)&out[((size_t)(b*SS)+q0+r1)*1024 + col] =
                make_float2(oc[2]+bb0, oc[3]+bb1);
        }
    }
}

// ============================================================================
extern "C" void kernel_launch(void* const* d_in, const int* in_sizes, int n_in,
                              void* d_out, int out_size)
{
    const float* query = (const float*)d_in[0];
    const float* key   = (const float*)d_in[1];
    const float* value = (const float*)d_in[2];
    const unsigned int* mask_w = (const unsigned int*)d_in[3];
    const float* in_w  = (const float*)d_in[4];
    const float* in_b  = (const float*)d_in[5];
    const float* out_w = (const float*)d_in[6];
    const float* out_b = (const float*)d_in[7];

    float* out      = (float*)d_out;                 // (B,S,E); kv fp16 until out-proj
    float* mean_out = out + (size_t)BB * SS * EE;    // (B,S,S)
    __half* kv      = (__half*)d_out;

    cudaFuncSetAttribute(fused_attn_kernel,
                         cudaFuncAttributeMaxDynamicSharedMemorySize, FUSED_SMEM);

    kv_proj_kernel<<<dim3(32, HH, BB), 256>>>(key, value, in_w, in_b, kv);

    fused_attn_kernel<<<dim3(SS / NQ, BB), 512, FUSED_SMEM>>>(
        query, in_w, in_b, mask_w, kv, out_w, out_b, mean_out, out);
}

// round 11
// speedup vs baseline: 3.9868x; 1.3967x over previous
#include <cuda_runtime.h>
#include <cuda_fp16.h>

#define BB 4
#define SS 1024
#define EE 1024
#define HH 16
#define DD 64
#define NQ 32
#define SCALE 0.125f
#define NBLK (BB * (SS / NQ))   // 128 fused blocks
#define NEGINF __int_as_float(0xff800000)

__device__ unsigned int g_bar;  // monotonic grid barrier (no reset needed)

// fused smem layout (bytes):
//   s_scores f32 [32][1032] = 132096   (also qproj staging / Wo fp16 staging / P~ fp16)
//   s_ctx    f16 [32][1032] =  66048
//   s_kt     f16 [128][72]  =  18432   (2 K tiles or 2 V tiles, row-major)
//   s_q16    f16 [32][72]   =   4608
//   s_keep   f32 [1024]     =   4096
//   s_inv    f32 [32]       =    128
#define SMB_CTX    132096
#define SMB_KT     (SMB_CTX + 66048)     // 198144
#define SMB_Q16    (SMB_KT + 18432)      // 216576
#define SMB_KEEP   (SMB_Q16 + 4608)      // 221184
#define SMB_INV    (SMB_KEEP + 4096)     // 225280
#define FUSED_SMEM (SMB_INV + 128)       // 225408 <= 227KB

#define KV_SMEM (2 * 64 * 264 * 2)       // 67584

// m16n8k16 row.col f32.f16.f16.f32
__device__ __forceinline__ void mma16816(float c[4], const unsigned a[4],
                                         const unsigned bf[2]) {
    asm volatile(
        "mma.sync.aligned.m16n8k16.row.col.f32.f16.f16.f32 "
        "{%0,%1,%2,%3}, {%4,%5,%6,%7}, {%8,%9}, {%0,%1,%2,%3};\n"
        : "+f"(c[0]), "+f"(c[1]), "+f"(c[2]), "+f"(c[3])
        : "r"(a[0]), "r"(a[1]), "r"(a[2]), "r"(a[3]), "r"(bf[0]), "r"(bf[1]));
}

__device__ __forceinline__ unsigned su32(const void* p) {
    unsigned a;
    asm("{ .reg .u64 t; cvta.to.shared.u64 t, %1; cvt.u32.u64 %0, t; }"
        : "=r"(a) : "l"(p));
    return a;
}

// canonical PV B-frag loader: V row-major [k][d], rows = k
__device__ __forceinline__ void ldmx2t(unsigned& r0, unsigned& r1, unsigned a) {
    asm volatile(
        "ldmatrix.sync.aligned.m8n8.x2.trans.shared.b16 {%0,%1}, [%2];\n"
        : "=r"(r0), "=r"(r1) : "r"(a));
}

// ============================================================================
// P1: K/V projection via HMMA -> fp16 into the (dead) output region.
// grid (2 which * 16 stiles, 16 h, 4 b), 256 threads (8 warps).
// Block computes [64 s][64 d]; warp w: m-tile (w>>1)*16, n-half (w&1)*32.
// ============================================================================
__global__ void __launch_bounds__(256, 2)
kv_proj_kernel(const float* __restrict__ key,
               const float* __restrict__ value,
               const float* __restrict__ in_w,
               const float* __restrict__ in_b,
               __half* __restrict__ kv)
{
    extern __shared__ char sm[];
    __half* Xs = (__half*)sm;                  // [64][264]
    __half* Ws = Xs + 64 * 264;                // [64][264]

    const int which = blockIdx.x >> 4;         // 0=k, 1=v
    const int s0 = (blockIdx.x & 15) * 64;
    const int h = blockIdx.y, b = blockIdx.z;
    const float* X = (which ? value : key) + (size_t)b * SS * EE;
    const int woff = (which ? 2048 : 1024) + h * 64;

    const int tid = threadIdx.x;
    const int wid = tid >> 5, lane = tid & 31;
    const int g = lane >> 2, t = lane & 3;
    const int mw = (wid >> 1) * 16;
    const int nh = (wid & 1) * 32;

    float acc[4][4];
    #pragma unroll
    for (int i = 0; i < 4; i++)
        #pragma unroll
        for (int j = 0; j < 4; j++) acc[i][j] = 0.0f;

    for (int e0 = 0; e0 < 1024; e0 += 256) {
        __syncthreads();
        for (int i = tid; i < 4096; i += 256) {
            const int r = i >> 6, c4 = i & 63;
            float4 v = *(const float4*)&X[(size_t)(s0 + r) * 1024 + e0 + c4 * 4];
            *(__half2*)&Xs[r*264 + c4*4]     = __floats2half2_rn(v.x, v.y);
            *(__half2*)&Xs[r*264 + c4*4 + 2] = __floats2half2_rn(v.z, v.w);
        }
        for (int i = tid; i < 4096; i += 256) {
            const int r = i >> 6, c4 = i & 63;
            float4 v = *(const float4*)&in_w[(size_t)(woff + r) * 1024 + e0 + c4 * 4];
            *(__half2*)&Ws[r*264 + c4*4]     = __floats2half2_rn(v.x, v.y);
            *(__half2*)&Ws[r*264 + c4*4 + 2] = __floats2half2_rn(v.z, v.w);
        }
        __syncthreads();

        #pragma unroll
        for (int ks = 0; ks < 16; ks++) {
            const int k0 = ks * 16;
            unsigned a[4];
            a[0] = *(const unsigned*)&Xs[(mw+g)*264 + k0 + t*2];
            a[1] = *(const unsigned*)&Xs[(mw+g+8)*264 + k0 + t*2];
            a[2] = *(const unsigned*)&Xs[(mw+g)*264 + k0 + t*2 + 8];
            a[3] = *(const unsigned*)&Xs[(mw+g+8)*264 + k0 + t*2 + 8];
            #pragma unroll
            for (int ns = 0; ns < 4; ns++) {
                const int n = nh + ns * 8;
                unsigned bf[2];
                bf[0] = *(const unsigned*)&Ws[(n+g)*264 + k0 + t*2];
                bf[1] = *(const unsigned*)&Ws[(n+g)*264 + k0 + t*2 + 8];
                mma16816(acc[ns], a, bf);
            }
        }
    }

    __half* dst = kv + (size_t)which * (BB*HH*SS*DD)
                     + ((size_t)(b * HH + h) * SS) * DD;
    #pragma unroll
    for (int ns = 0; ns < 4; ns++) {
        const int n = nh + ns * 8;
        const float b0 = in_b[woff + n + t*2];
        const float b1 = in_b[woff + n + t*2 + 1];
        *(__half2*)&dst[(size_t)(s0+mw+g)*DD + n + t*2] =
            __floats2half2_rn(acc[ns][0] + b0, acc[ns][1] + b1);
        *(__half2*)&dst[(size_t)(s0+mw+g+8)*DD + n + t*2] =
            __floats2half2_rn(acc[ns][2] + b0, acc[ns][3] + b1);
    }
}

// ============================================================================
// P2: fused attention + out-projection, tensor-core edition. 512 threads.
// ============================================================================
__global__ void __launch_bounds__(512, 1)
fused_attn_kernel(const float* __restrict__ query,
                  const float* __restrict__ in_w,
                  const float* __restrict__ in_b,
                  const unsigned int* __restrict__ mask_w,
                  const __half* __restrict__ kv,
                  const float* __restrict__ out_w,
                  const float* __restrict__ out_b,
                  float* __restrict__ mean_out,
                  float* __restrict__ out)
{
    extern __shared__ char smem[];
    float*  s_scores = (float*)smem;                 // [32][1032] f32
    __half* s_ctx    = (__half*)(smem + SMB_CTX);    // [32][1032] f16
    __half* s_kt     = (__half*)(smem + SMB_KT);     // [128][72] f16 (2 tiles)
    __half* s_q16    = (__half*)(smem + SMB_Q16);    // [32][72] f16
    float*  s_keep   = (float*)(smem + SMB_KEEP);
    float*  s_inv    = (float*)(smem + SMB_INV);

    const int qt = blockIdx.x, b = blockIdx.y;
    const int q0 = qt * NQ;
    const int tid = threadIdx.x;
    const int wid = tid >> 5, lane = tid & 31;
    const int g = lane >> 2, t = lane & 3;
    const int mw = (wid >> 3) * 16;   // 0|16
    const int nw = (wid & 7) * 8;     // 0..56

    for (int i = tid; i < 1024; i += 512)
        s_keep[i] = (mask_w[b * SS + i] != 0u) ? 1.0f : 0.0f;

    for (int h = 0; h < HH; h++) {
        const __half* Kb = kv + ((size_t)(b * HH + h) * SS) * DD;
        const __half* Vb = Kb + (size_t)(BB*HH*SS*DD);

        // ---------- Q-proj (mma) ----------
        {
            __half* qst = (__half*)smem;          // [32][264]
            __half* wst = qst + 32 * 264;         // [64][264]
            float qc[4] = {0.f, 0.f, 0.f, 0.f};

            for (int e0 = 0; e0 < 1024; e0 += 256) {
                __syncthreads();
                for (int i = tid; i < 2048; i += 512) {
                    const int r = i >> 6, c4 = i & 63;
                    float4 v = *(const float4*)&query[((size_t)(b*SS)+q0+r)*1024 + e0 + c4*4];
                    *(__half2*)&qst[r*264 + c4*4]     = __floats2half2_rn(v.x, v.y);
                    *(__half2*)&qst[r*264 + c4*4 + 2] = __floats2half2_rn(v.z, v.w);
                }
                for (int i = tid; i < 4096; i += 512) {
                    const int r = i >> 6, c4 = i & 63;
                    float4 v = *(const float4*)&in_w[(size_t)(h*64+r)*1024 + e0 + c4*4];
                    *(__half2*)&wst[r*264 + c4*4]     = __floats2half2_rn(v.x, v.y);
                    *(__half2*)&wst[r*264 + c4*4 + 2] = __floats2half2_rn(v.z, v.w);
                }
                __syncthreads();

                #pragma unroll
                for (int ks = 0; ks < 16; ks++) {
                    const int k0 = ks * 16;
                    unsigned a[4], bf[2];
                    a[0] = *(const unsigned*)&qst[(mw+g)*264 + k0 + t*2];
                    a[1] = *(const unsigned*)&qst[(mw+g+8)*264 + k0 + t*2];
                    a[2] = *(const unsigned*)&qst[(mw+g)*264 + k0 + t*2 + 8];
                    a[3] = *(const unsigned*)&qst[(mw+g+8)*264 + k0 + t*2 + 8];
                    bf[0] = *(const unsigned*)&wst[(nw+g)*264 + k0 + t*2];
                    bf[1] = *(const unsigned*)&wst[(nw+g)*264 + k0 + t*2 + 8];
                    mma16816(qc, a, bf);
                }
            }
            const float bb0 = in_b[h*64 + nw + t*2];
            const float bb1 = in_b[h*64 + nw + t*2 + 1];
            *(__half2*)&s_q16[(mw+g)*72 + nw + t*2]   = __floats2half2_rn(qc[0]+bb0, qc[1]+bb1);
            *(__half2*)&s_q16[(mw+g+8)*72 + nw + t*2] = __floats2half2_rn(qc[2]+bb0, qc[3]+bb1);
        }
        __syncthreads();

        // hoisted A-frags (Q): same for all k-tiles
        unsigned aq[4][4];
        #pragma unroll
        for (int ks = 0; ks < 4; ks++) {
            const int k0 = ks * 16;
            aq[ks][0] = *(const unsigned*)&s_q16[(mw+g)*72 + k0 + t*2];
            aq[ks][1] = *(const unsigned*)&s_q16[(mw+g+8)*72 + k0 + t*2];
            aq[ks][2] = *(const unsigned*)&s_q16[(mw+g)*72 + k0 + t*2 + 8];
            aq[ks][3] = *(const unsigned*)&s_q16[(mw+g+8)*72 + k0 + t*2 + 8];
        }

        // ---------- scores (mma), 2 k-tiles per stage round ----------
        for (int rd = 0; rd < 8; rd++) {
            __syncthreads();
            for (int i = tid; i < 2048; i += 512) {      // 128 rows x 16 uint2
                const int r = i >> 4, c8 = i & 15;
                *(uint2*)&s_kt[r*72 + c8*4] =
                    *(const uint2*)&Kb[(size_t)(rd*128 + r)*64 + c8*4];
            }
            __syncthreads();

            #pragma unroll
            for (int kt2 = 0; kt2 < 2; kt2++) {
                float sc4[4] = {0.f, 0.f, 0.f, 0.f};
                #pragma unroll
                for (int ks = 0; ks < 4; ks++) {
                    const int k0 = ks * 16;
                    unsigned bf[2];
                    bf[0] = *(const unsigned*)&s_kt[(kt2*64 + nw+g)*72 + k0 + t*2];
                    bf[1] = *(const unsigned*)&s_kt[(kt2*64 + nw+g)*72 + k0 + t*2 + 8];
                    mma16816(sc4, aq[ks], bf);
                }

                const int kg = rd*128 + kt2*64 + nw + t*2;
                const float kf0 = s_keep[kg], kf1 = s_keep[kg+1];
                const int r0 = mw + g, r1 = mw + g + 8;
                float v00 = sc4[0]*SCALE + (float)(q0 + r0 - kg);
                float v01 = sc4[1]*SCALE + (float)(q0 + r0 - kg - 1);
                float v10 = sc4[2]*SCALE + (float)(q0 + r1 - kg);
                float v11 = sc4[3]*SCALE + (float)(q0 + r1 - kg - 1);
                v00 = (kf0 != 0.f) ? v00 : NEGINF;
                v01 = (kf1 != 0.f) ? v01 : NEGINF;
                v10 = (kf0 != 0.f) ? v10 : NEGINF;
                v11 = (kf1 != 0.f) ? v11 : NEGINF;
                *(float2*)&s_scores[r0*1032 + kg] = make_float2(v00, v01);
                *(float2*)&s_scores[r1*1032 + kg] = make_float2(v10, v11);
            }
        }
        __syncthreads();

        // ---------- softmax (warp/row); P~ fp16 in place; mean from regs ----------
        for (int r = wid; r < 32; r += 16) {
            float* srow = s_scores + r * 1032;
            __half* prow = (__half*)srow;

            float mx = NEGINF;
            #pragma unroll
            for (int i = 0; i < 32; i++) mx = fmaxf(mx, srow[lane + 32*i]);
            #pragma unroll
            for (int m = 16; m >= 1; m >>= 1)
                mx = fmaxf(mx, __shfl_xor_sync(0xffffffffu, mx, m));

            float pv[32];
            float sum = 0.f;
            #pragma unroll
            for (int i = 0; i < 32; i++) {
                const float p = __expf(srow[lane + 32*i] - mx);
                pv[i] = p; sum += p;
            }
            #pragma unroll
            for (int m = 16; m >= 1; m >>= 1)
                sum += __shfl_xor_sync(0xffffffffu, sum, m);

            const float inv = 1.0f / sum;
            if (lane == 0) s_inv[r] = inv;

            #pragma unroll
            for (int i = 0; i < 32; i++)
                prow[lane + 32*i] = __float2half(pv[i]);

            float* mrow = mean_out + ((size_t)(b*SS) + q0 + r) * SS;
            const float msc = inv * 0.0625f;
            if (h == 0) {
                #pragma unroll
                for (int i = 0; i < 32; i++) mrow[lane + 32*i] = pv[i] * msc;
            } else {
                #pragma unroll
                for (int i = 0; i < 32; i++) mrow[lane + 32*i] += pv[i] * msc;
            }
        }
        __syncthreads();

        // ---------- PV (mma): V staged row-major, B-frags via ldmatrix.trans ----------
        {
            float cacc[4] = {0.f, 0.f, 0.f, 0.f};
            const char* pbase = (const char*)s_scores + (size_t)(mw+g)*4128;
            const char* pbase8 = (const char*)s_scores + (size_t)(mw+g+8)*4128;

            for (int rd = 0; rd < 8; rd++) {
                __syncthreads();
                for (int i = tid; i < 2048; i += 512) {   // V rows straight copy
                    const int r = i >> 4, c8 = i & 15;
                    *(uint2*)&s_kt[r*72 + c8*4] =
                        *(const uint2*)&Vb[(size_t)(rd*128 + r)*64 + c8*4];
                }
                __syncthreads();

                #pragma unroll
                for (int kt2 = 0; kt2 < 2; kt2++) {
                    #pragma unroll
                    for (int ks = 0; ks < 4; ks++) {
                        const int kk = rd*128 + kt2*64 + ks*16 + t*2;
                        unsigned a[4], bf[2];
                        a[0] = *(const unsigned*)(pbase + kk*2);
                        a[1] = *(const unsigned*)(pbase8 + kk*2);
                        a[2] = *(const unsigned*)(pbase + (kk+8)*2);
                        a[3] = *(const unsigned*)(pbase8 + (kk+8)*2);
                        const int krow = kt2*64 + ks*16 + (lane & 15);
                        ldmx2t(bf[0], bf[1], su32(&s_kt[krow*72 + nw]));
                        mma16816(cacc, a, bf);
                    }
                }
            }
            const int r0 = mw + g, r1 = mw + g + 8;
            const float i0 = s_inv[r0], i1 = s_inv[r1];
            *(__half2*)&s_ctx[r0*1032 + h*64 + nw + t*2] =
                __floats2half2_rn(cacc[0]*i0, cacc[1]*i0);
            *(__half2*)&s_ctx[r1*1032 + h*64 + nw + t*2] =
                __floats2half2_rn(cacc[2]*i1, cacc[3]*i1);
        }
        __syncthreads();
    }

    // ==================== grid barrier ====================
    if (tid == 0) {
        __threadfence();
        const unsigned int old = atomicAdd(&g_bar, 1u);
        const unsigned int target = (old / NBLK + 1u) * NBLK;
        while (atomicAdd(&g_bar, 0u) < target) { }
    }
    __syncthreads();

    // ==================== out-proj (mma): out = ctx @ Wo^T + bias ====================
    {
        __half* woS = (__half*)smem;              // [64][1032] fp16 (scores dead)
        for (int n0 = 0; n0 < 1024; n0 += 64) {
            __syncthreads();
            for (int i = tid; i < 16384; i += 512) {
                const int r = i >> 8, c4 = i & 255;
                float4 v = *(const float4*)&out_w[(size_t)(n0 + r)*1024 + c4*4];
                *(__half2*)&woS[r*1032 + c4*4]     = __floats2half2_rn(v.x, v.y);
                *(__half2*)&woS[r*1032 + c4*4 + 2] = __floats2half2_rn(v.z, v.w);
            }
            __syncthreads();

            float oc[4] = {0.f, 0.f, 0.f, 0.f};
            #pragma unroll 4
            for (int ks = 0; ks < 64; ks++) {
                const int k0 = ks * 16;
                unsigned a[4], bf[2];
                a[0] = *(const unsigned*)&s_ctx[(mw+g)*1032 + k0 + t*2];
                a[1] = *(const unsigned*)&s_ctx[(mw+g+8)*1032 + k0 + t*2];
                a[2] = *(const unsigned*)&s_ctx[(mw+g)*1032 + k0 + t*2 + 8];
                a[3] = *(const unsigned*)&s_ctx[(mw+g+8)*1032 + k0 + t*2 + 8];
                bf[0] = *(const unsigned*)&woS[(nw+g)*1032 + k0 + t*2];
                bf[1] = *(const unsigned*)&woS[(nw+g)*1032 + k0 + t*2 + 8];
                mma16816(oc, a, bf);
            }

            const int col = n0 + nw + t*2;
            const float bb0 = out_b[col], bb1 = out_b[col+1];
            const int r0 = mw + g, r1 = mw + g + 8;
            *(float2*)&out[((size_t)(b*SS)+q0+r0)*1024 + col] =
                make_float2(oc[0]+bb0, oc[1]+bb1);
            *(float2*)&out[((size_t)(b*SS)+q0+r1)*1024 + col] =
                make_float2(oc[2]+bb0, oc[3]+bb1);
        }
    }
}

// ============================================================================
extern "C" void kernel_launch(void* const* d_in, const int* in_sizes, int n_in,
                              void* d_out, int out_size)
{
    const float* query = (const float*)d_in[0];
    const float* key   = (const float*)d_in[1];
    const float* value = (const float*)d_in[2];
    const unsigned int* mask_w = (const unsigned int*)d_in[3];
    const float* in_w  = (const float*)d_in[4];
    const float* in_b  = (const float*)d_in[5];
    const float* out_w = (const float*)d_in[6];
    const float* out_b = (const float*)d_in[7];

    float* out      = (float*)d_out;                 // (B,S,E); kv fp16 until out-proj
    float* mean_out = out + (size_t)BB * SS * EE;    // (B,S,S)
    __half* kv      = (__half*)d_out;

    cudaFuncSetAttribute(fused_attn_kernel,
                         cudaFuncAttributeMaxDynamicSharedMemorySize, FUSED_SMEM);
    cudaFuncSetAttribute(kv_proj_kernel,
                         cudaFuncAttributeMaxDynamicSharedMemorySize, KV_SMEM);

    kv_proj_kernel<<<dim3(32, HH, BB), 256, KV_SMEM>>>(key, value, in_w, in_b, kv);

    fused_attn_kernel<<<dim3(SS / NQ, BB), 512, FUSED_SMEM>>>(
        query, in_w, in_b, mask_w, kv, out_w, out_b, mean_out, out);
}

// round 12
// speedup vs baseline: 5.0019x; 1.2546x over previous
#include <cuda_runtime.h>
#include <cuda_fp16.h>

#define BB 4
#define SS 1024
#define EE 1024
#define HH 16
#define DD 64
#define NQ 32
#define SCALE 0.125f
#define NBLK (BB * (SS / NQ))   // 128 fused blocks
#define NEGINF __int_as_float(0xff800000)

__device__ unsigned int g_bar;  // monotonic grid barrier (no reset needed)

// fused smem layout (bytes):
//   s_scores f32 [32][1032] = 132096   (also qproj staging / Wo fp16 staging / P~ fp16)
//   s_ctx    f16 [32][1032] =  66048
//   s_kt     f16 [2][64][72]=  18432   (double-buffered K or V tiles, row-major)
//   s_q16    f16 [32][72]   =   4608
//   s_keep   f32 [1024]     =   4096
//   s_inv    f32 [32]       =    128
#define SMB_CTX    132096
#define SMB_KT     (SMB_CTX + 66048)     // 198144 (16B aligned)
#define SMB_Q16    (SMB_KT + 18432)      // 216576
#define SMB_KEEP   (SMB_Q16 + 4608)      // 221184
#define SMB_INV    (SMB_KEEP + 4096)     // 225280
#define FUSED_SMEM (SMB_INV + 128)       // 225408 <= 227KB

#define KV_SMEM (2 * 64 * 264 * 2)       // 67584
#define KTBUF 4608                        // halfs per 64-row buffer

// m16n8k16 row.col f32.f16.f16.f32
__device__ __forceinline__ void mma16816(float c[4], const unsigned a[4],
                                         const unsigned bf[2]) {
    asm volatile(
        "mma.sync.aligned.m16n8k16.row.col.f32.f16.f16.f32 "
        "{%0,%1,%2,%3}, {%4,%5,%6,%7}, {%8,%9}, {%0,%1,%2,%3};\n"
        : "+f"(c[0]), "+f"(c[1]), "+f"(c[2]), "+f"(c[3])
        : "r"(a[0]), "r"(a[1]), "r"(a[2]), "r"(a[3]), "r"(bf[0]), "r"(bf[1]));
}

__device__ __forceinline__ unsigned su32(const void* p) {
    unsigned a;
    asm("{ .reg .u64 t; cvta.to.shared.u64 t, %1; cvt.u32.u64 %0, t; }"
        : "=r"(a) : "l"(p));
    return a;
}

__device__ __forceinline__ void cp16(unsigned dst, const void* src) {
    asm volatile("cp.async.ca.shared.global [%0], [%1], 16;\n"
                 :: "r"(dst), "l"(src));
}
#define CP_COMMIT() asm volatile("cp.async.commit_group;\n")
#define CP_WAIT0()  asm volatile("cp.async.wait_group 0;\n")

// canonical PV B-frag loader: V row-major [k][d], rows = k
__device__ __forceinline__ void ldmx2t(unsigned& r0, unsigned& r1, unsigned a) {
    asm volatile(
        "ldmatrix.sync.aligned.m8n8.x2.trans.shared.b16 {%0,%1}, [%2];\n"
        : "=r"(r0), "=r"(r1) : "r"(a));
}

// ============================================================================
// P1: K/V projection via HMMA -> fp16 into the (dead) output region.
// ============================================================================
__global__ void __launch_bounds__(256, 2)
kv_proj_kernel(const float* __restrict__ key,
               const float* __restrict__ value,
               const float* __restrict__ in_w,
               const float* __restrict__ in_b,
               __half* __restrict__ kv)
{
    extern __shared__ char sm[];
    __half* Xs = (__half*)sm;                  // [64][264]
    __half* Ws = Xs + 64 * 264;                // [64][264]

    const int which = blockIdx.x >> 4;         // 0=k, 1=v
    const int s0 = (blockIdx.x & 15) * 64;
    const int h = blockIdx.y, b = blockIdx.z;
    const float* X = (which ? value : key) + (size_t)b * SS * EE;
    const int woff = (which ? 2048 : 1024) + h * 64;

    const int tid = threadIdx.x;
    const int wid = tid >> 5, lane = tid & 31;
    const int g = lane >> 2, t = lane & 3;
    const int mw = (wid >> 1) * 16;
    const int nh = (wid & 1) * 32;

    float acc[4][4];
    #pragma unroll
    for (int i = 0; i < 4; i++)
        #pragma unroll
        for (int j = 0; j < 4; j++) acc[i][j] = 0.0f;

    for (int e0 = 0; e0 < 1024; e0 += 256) {
        __syncthreads();
        for (int i = tid; i < 4096; i += 256) {
            const int r = i >> 6, c4 = i & 63;
            float4 v = *(const float4*)&X[(size_t)(s0 + r) * 1024 + e0 + c4 * 4];
            *(__half2*)&Xs[r*264 + c4*4]     = __floats2half2_rn(v.x, v.y);
            *(__half2*)&Xs[r*264 + c4*4 + 2] = __floats2half2_rn(v.z, v.w);
        }
        for (int i = tid; i < 4096; i += 256) {
            const int r = i >> 6, c4 = i & 63;
            float4 v = *(const float4*)&in_w[(size_t)(woff + r) * 1024 + e0 + c4 * 4];
            *(__half2*)&Ws[r*264 + c4*4]     = __floats2half2_rn(v.x, v.y);
            *(__half2*)&Ws[r*264 + c4*4 + 2] = __floats2half2_rn(v.z, v.w);
        }
        __syncthreads();

        #pragma unroll
        for (int ks = 0; ks < 16; ks++) {
            const int k0 = ks * 16;
            unsigned a[4];
            a[0] = *(const unsigned*)&Xs[(mw+g)*264 + k0 + t*2];
            a[1] = *(const unsigned*)&Xs[(mw+g+8)*264 + k0 + t*2];
            a[2] = *(const unsigned*)&Xs[(mw+g)*264 + k0 + t*2 + 8];
            a[3] = *(const unsigned*)&Xs[(mw+g+8)*264 + k0 + t*2 + 8];
            #pragma unroll
            for (int ns = 0; ns < 4; ns++) {
                const int n = nh + ns * 8;
                unsigned bf[2];
                bf[0] = *(const unsigned*)&Ws[(n+g)*264 + k0 + t*2];
                bf[1] = *(const unsigned*)&Ws[(n+g)*264 + k0 + t*2 + 8];
                mma16816(acc[ns], a, bf);
            }
        }
    }

    __half* dst = kv + (size_t)which * (BB*HH*SS*DD)
                     + ((size_t)(b * HH + h) * SS) * DD;
    #pragma unroll
    for (int ns = 0; ns < 4; ns++) {
        const int n = nh + ns * 8;
        const float b0 = in_b[woff + n + t*2];
        const float b1 = in_b[woff + n + t*2 + 1];
        *(__half2*)&dst[(size_t)(s0+mw+g)*DD + n + t*2] =
            __floats2half2_rn(acc[ns][0] + b0, acc[ns][1] + b1);
        *(__half2*)&dst[(size_t)(s0+mw+g+8)*DD + n + t*2] =
            __floats2half2_rn(acc[ns][2] + b0, acc[ns][3] + b1);
    }
}

// ============================================================================
// P2: fused attention + out-projection, tensor-core + cp.async edition.
// ============================================================================
__global__ void __launch_bounds__(512, 1)
fused_attn_kernel(const float* __restrict__ query,
                  const float* __restrict__ in_w,
                  const float* __restrict__ in_b,
                  const unsigned int* __restrict__ mask_w,
                  const __half* __restrict__ kv,
                  const float* __restrict__ out_w,
                  const float* __restrict__ out_b,
                  float* __restrict__ mean_out,
                  float* __restrict__ out)
{
    extern __shared__ char smem[];
    float*  s_scores = (float*)smem;                 // [32][1032] f32
    __half* s_ctx    = (__half*)(smem + SMB_CTX);    // [32][1032] f16
    __half* s_kt     = (__half*)(smem + SMB_KT);     // [2][64][72] f16
    __half* s_q16    = (__half*)(smem + SMB_Q16);    // [32][72] f16
    float*  s_keep   = (float*)(smem + SMB_KEEP);
    float*  s_inv    = (float*)(smem + SMB_INV);

    const int qt = blockIdx.x, b = blockIdx.y;
    const int q0 = qt * NQ;
    const int tid = threadIdx.x;
    const int wid = tid >> 5, lane = tid & 31;
    const int g = lane >> 2, t = lane & 3;
    const int mw = (wid >> 3) * 16;   // 0|16
    const int nw = (wid & 7) * 8;     // 0..56
    const int str = tid >> 3;         // stage row 0..63
    const int stc = tid & 7;          // stage 16B chunk 0..7

    for (int i = tid; i < 1024; i += 512)
        s_keep[i] = (mask_w[b * SS + i] != 0u) ? 1.0f : 0.0f;

    for (int h = 0; h < HH; h++) {
        const __half* Kb = kv + ((size_t)(b * HH + h) * SS) * DD;
        const __half* Vb = Kb + (size_t)(BB*HH*SS*DD);

        // ---------- Q-proj (mma, dual acc) ----------
        {
            __half* qst = (__half*)smem;          // [32][264]
            __half* wst = qst + 32 * 264;         // [64][264]
            float qc0[4] = {0.f,0.f,0.f,0.f}, qc1[4] = {0.f,0.f,0.f,0.f};

            for (int e0 = 0; e0 < 1024; e0 += 256) {
                __syncthreads();
                for (int i = tid; i < 2048; i += 512) {
                    const int r = i >> 6, c4 = i & 63;
                    float4 v = *(const float4*)&query[((size_t)(b*SS)+q0+r)*1024 + e0 + c4*4];
                    *(__half2*)&qst[r*264 + c4*4]     = __floats2half2_rn(v.x, v.y);
                    *(__half2*)&qst[r*264 + c4*4 + 2] = __floats2half2_rn(v.z, v.w);
                }
                for (int i = tid; i < 4096; i += 512) {
                    const int r = i >> 6, c4 = i & 63;
                    float4 v = *(const float4*)&in_w[(size_t)(h*64+r)*1024 + e0 + c4*4];
                    *(__half2*)&wst[r*264 + c4*4]     = __floats2half2_rn(v.x, v.y);
                    *(__half2*)&wst[r*264 + c4*4 + 2] = __floats2half2_rn(v.z, v.w);
                }
                __syncthreads();

                #pragma unroll
                for (int ks = 0; ks < 16; ks++) {
                    const int k0 = ks * 16;
                    unsigned a[4], bf[2];
                    a[0] = *(const unsigned*)&qst[(mw+g)*264 + k0 + t*2];
                    a[1] = *(const unsigned*)&qst[(mw+g+8)*264 + k0 + t*2];
                    a[2] = *(const unsigned*)&qst[(mw+g)*264 + k0 + t*2 + 8];
                    a[3] = *(const unsigned*)&qst[(mw+g+8)*264 + k0 + t*2 + 8];
                    bf[0] = *(const unsigned*)&wst[(nw+g)*264 + k0 + t*2];
                    bf[1] = *(const unsigned*)&wst[(nw+g)*264 + k0 + t*2 + 8];
                    if (ks & 1) mma16816(qc1, a, bf);
                    else        mma16816(qc0, a, bf);
                }
            }
            const float bb0 = in_b[h*64 + nw + t*2];
            const float bb1 = in_b[h*64 + nw + t*2 + 1];
            *(__half2*)&s_q16[(mw+g)*72 + nw + t*2] =
                __floats2half2_rn(qc0[0]+qc1[0]+bb0, qc0[1]+qc1[1]+bb1);
            *(__half2*)&s_q16[(mw+g+8)*72 + nw + t*2] =
                __floats2half2_rn(qc0[2]+qc1[2]+bb0, qc0[3]+qc1[3]+bb1);
        }
        __syncthreads();

        // hoisted A-frags (Q): same for all k-tiles
        unsigned aq[4][4];
        #pragma unroll
        for (int ks = 0; ks < 4; ks++) {
            const int k0 = ks * 16;
            aq[ks][0] = *(const unsigned*)&s_q16[(mw+g)*72 + k0 + t*2];
            aq[ks][1] = *(const unsigned*)&s_q16[(mw+g+8)*72 + k0 + t*2];
            aq[ks][2] = *(const unsigned*)&s_q16[(mw+g)*72 + k0 + t*2 + 8];
            aq[ks][3] = *(const unsigned*)&s_q16[(mw+g+8)*72 + k0 + t*2 + 8];
        }

        // ---------- scores (mma, cp.async double-buffered K) ----------
        {
            cp16(su32(&s_kt[str*72 + stc*8]), &Kb[(size_t)str*64 + stc*8]);
            CP_COMMIT(); CP_WAIT0();
            __syncthreads();

            for (int kt = 0; kt < 16; kt++) {
                const int buf = (kt & 1) * KTBUF;
                if (kt < 15) {
                    cp16(su32(&s_kt[((kt+1)&1)*KTBUF + str*72 + stc*8]),
                         &Kb[(size_t)((kt+1)*64 + str)*64 + stc*8]);
                    CP_COMMIT();
                }

                float sc0[4] = {0.f,0.f,0.f,0.f}, sc1[4] = {0.f,0.f,0.f,0.f};
                #pragma unroll
                for (int ks = 0; ks < 4; ks++) {
                    const int k0 = ks * 16;
                    unsigned bf[2];
                    bf[0] = *(const unsigned*)&s_kt[buf + (nw+g)*72 + k0 + t*2];
                    bf[1] = *(const unsigned*)&s_kt[buf + (nw+g)*72 + k0 + t*2 + 8];
                    if (ks & 1) mma16816(sc1, aq[ks], bf);
                    else        mma16816(sc0, aq[ks], bf);
                }

                const int kg = kt*64 + nw + t*2;
                const float kf0 = s_keep[kg], kf1 = s_keep[kg+1];
                const int r0 = mw + g, r1 = mw + g + 8;
                float v00 = (sc0[0]+sc1[0])*SCALE + (float)(q0 + r0 - kg);
                float v01 = (sc0[1]+sc1[1])*SCALE + (float)(q0 + r0 - kg - 1);
                float v10 = (sc0[2]+sc1[2])*SCALE + (float)(q0 + r1 - kg);
                float v11 = (sc0[3]+sc1[3])*SCALE + (float)(q0 + r1 - kg - 1);
                v00 = (kf0 != 0.f) ? v00 : NEGINF;
                v01 = (kf1 != 0.f) ? v01 : NEGINF;
                v10 = (kf0 != 0.f) ? v10 : NEGINF;
                v11 = (kf1 != 0.f) ? v11 : NEGINF;
                *(float2*)&s_scores[r0*1032 + kg] = make_float2(v00, v01);
                *(float2*)&s_scores[r1*1032 + kg] = make_float2(v10, v11);

                if (kt < 15) CP_WAIT0();
                __syncthreads();
            }
        }

        // ---------- softmax (warp/row); P~ fp16 in place; mean from regs ----------
        for (int r = wid; r < 32; r += 16) {
            float* srow = s_scores + r * 1032;
            __half* prow = (__half*)srow;

            float mx = NEGINF;
            #pragma unroll
            for (int i = 0; i < 32; i++) mx = fmaxf(mx, srow[lane + 32*i]);
            #pragma unroll
            for (int m = 16; m >= 1; m >>= 1)
                mx = fmaxf(mx, __shfl_xor_sync(0xffffffffu, mx, m));

            float pv[32];
            float sum = 0.f;
            #pragma unroll
            for (int i = 0; i < 32; i++) {
                const float p = __expf(srow[lane + 32*i] - mx);
                pv[i] = p; sum += p;
            }
            #pragma unroll
            for (int m = 16; m >= 1; m >>= 1)
                sum += __shfl_xor_sync(0xffffffffu, sum, m);

            const float inv = 1.0f / sum;
            if (lane == 0) s_inv[r] = inv;

            #pragma unroll
            for (int i = 0; i < 32; i++)
                prow[lane + 32*i] = __float2half(pv[i]);

            float* mrow = mean_out + ((size_t)(b*SS) + q0 + r) * SS;
            const float msc = inv * 0.0625f;
            if (h == 0) {
                #pragma unroll
                for (int i = 0; i < 32; i++) mrow[lane + 32*i] = pv[i] * msc;
            } else {
                #pragma unroll
                for (int i = 0; i < 32; i++) mrow[lane + 32*i] += pv[i] * msc;
            }
        }
        __syncthreads();

        // ---------- PV (mma, cp.async double-buffered V, ldmatrix.trans) ----------
        {
            float ca0[4] = {0.f,0.f,0.f,0.f}, ca1[4] = {0.f,0.f,0.f,0.f};
            const char* pbase = (const char*)s_scores + (size_t)(mw+g)*4128;
            const char* pbase8 = (const char*)s_scores + (size_t)(mw+g+8)*4128;

            cp16(su32(&s_kt[str*72 + stc*8]), &Vb[(size_t)str*64 + stc*8]);
            CP_COMMIT(); CP_WAIT0();
            __syncthreads();

            for (int kt = 0; kt < 16; kt++) {
                const int buf = (kt & 1) * KTBUF;
                if (kt < 15) {
                    cp16(su32(&s_kt[((kt+1)&1)*KTBUF + str*72 + stc*8]),
                         &Vb[(size_t)((kt+1)*64 + str)*64 + stc*8]);
                    CP_COMMIT();
                }

                #pragma unroll
                for (int ks = 0; ks < 4; ks++) {
                    const int kk = kt*64 + ks*16 + t*2;
                    unsigned a[4], bf[2];
                    a[0] = *(const unsigned*)(pbase + kk*2);
                    a[1] = *(const unsigned*)(pbase8 + kk*2);
                    a[2] = *(const unsigned*)(pbase + (kk+8)*2);
                    a[3] = *(const unsigned*)(pbase8 + (kk+8)*2);
                    const int krow = ks*16 + (lane & 15);
                    ldmx2t(bf[0], bf[1], su32(&s_kt[buf + krow*72 + nw]));
                    if (ks & 1) mma16816(ca1, a, bf);
                    else        mma16816(ca0, a, bf);
                }

                if (kt < 15) CP_WAIT0();
                __syncthreads();
            }

            const int r0 = mw + g, r1 = mw + g + 8;
            const float i0 = s_inv[r0], i1 = s_inv[r1];
            *(__half2*)&s_ctx[r0*1032 + h*64 + nw + t*2] =
                __floats2half2_rn((ca0[0]+ca1[0])*i0, (ca0[1]+ca1[1])*i0);
            *(__half2*)&s_ctx[r1*1032 + h*64 + nw + t*2] =
                __floats2half2_rn((ca0[2]+ca1[2])*i1, (ca0[3]+ca1[3])*i1);
        }
        __syncthreads();
    }

    // ==================== grid barrier ====================
    if (tid == 0) {
        __threadfence();
        const unsigned int old = atomicAdd(&g_bar, 1u);
        const unsigned int target = (old / NBLK + 1u) * NBLK;
        while (atomicAdd(&g_bar, 0u) < target) { }
    }
    __syncthreads();

    // ==================== out-proj (mma, dual acc): out = ctx @ Wo^T + bias ====
    {
        __half* woS = (__half*)smem;              // [64][1032] fp16 (scores dead)
        for (int n0 = 0; n0 < 1024; n0 += 64) {
            __syncthreads();
            for (int i = tid; i < 16384; i += 512) {
                const int r = i >> 8, c4 = i & 255;
                float4 v = *(const float4*)&out_w[(size_t)(n0 + r)*1024 + c4*4];
                *(__half2*)&woS[r*1032 + c4*4]     = __floats2half2_rn(v.x, v.y);
                *(__half2*)&woS[r*1032 + c4*4 + 2] = __floats2half2_rn(v.z, v.w);
            }
            __syncthreads();

            float oc0[4] = {0.f,0.f,0.f,0.f}, oc1[4] = {0.f,0.f,0.f,0.f};
            #pragma unroll 8
            for (int ks = 0; ks < 64; ks++) {
                const int k0 = ks * 16;
                unsigned a[4], bf[2];
                a[0] = *(const unsigned*)&s_ctx[(mw+g)*1032 + k0 + t*2];
                a[1] = *(const unsigned*)&s_ctx[(mw+g+8)*1032 + k0 + t*2];
                a[2] = *(const unsigned*)&s_ctx[(mw+g)*1032 + k0 + t*2 + 8];
                a[3] = *(const unsigned*)&s_ctx[(mw+g+8)*1032 + k0 + t*2 + 8];
                bf[0] = *(const unsigned*)&woS[(nw+g)*1032 + k0 + t*2];
                bf[1] = *(const unsigned*)&woS[(nw+g)*1032 + k0 + t*2 + 8];
                if (ks & 1) mma16816(oc1, a, bf);
                else        mma16816(oc0, a, bf);
            }

            const int col = n0 + nw + t*2;
            const float bb0 = out_b[col], bb1 = out_b[col+1];
            const int r0 = mw + g, r1 = mw + g + 8;
            *(float2*)&out[((size_t)(b*SS)+q0+r0)*1024 + col] =
                make_float2(oc0[0]+oc1[0]+bb0, oc0[1]+oc1[1]+bb1);
            *(float2*)&out[((size_t)(b*SS)+q0+r1)*1024 + col] =
                make_float2(oc0[2]+oc1[2]+bb0, oc0[3]+oc1[3]+bb1);
        }
    }
}

// ============================================================================
extern "C" void kernel_launch(void* const* d_in, const int* in_sizes, int n_in,
                              void* d_out, int out_size)
{
    const float* query = (const float*)d_in[0];
    const float* key   = (const float*)d_in[1];
    const float* value = (const float*)d_in[2];
    const unsigned int* mask_w = (const unsigned int*)d_in[3];
    const float* in_w  = (const float*)d_in[4];
    const float* in_b  = (const float*)d_in[5];
    const float* out_w = (const float*)d_in[6];
    const float* out_b = (const float*)d_in[7];

    float* out      = (float*)d_out;                 // (B,S,E); kv fp16 until out-proj
    float* mean_out = out + (size_t)BB * SS * EE;    // (B,S,S)
    __half* kv      = (__half*)d_out;

    cudaFuncSetAttribute(fused_attn_kernel,
                         cudaFuncAttributeMaxDynamicSharedMemorySize, FUSED_SMEM);
    cudaFuncSetAttribute(kv_proj_kernel,
                         cudaFuncAttributeMaxDynamicSharedMemorySize, KV_SMEM);

    kv_proj_kernel<<<dim3(32, HH, BB), 256, KV_SMEM>>>(key, value, in_w, in_b, kv);

    fused_attn_kernel<<<dim3(SS / NQ, BB), 512, FUSED_SMEM>>>(
        query, in_w, in_b, mask_w, kv, out_w, out_b, mean_out, out);
}

// round 14
// speedup vs baseline: 5.4264x; 1.0849x over previous
#include <cuda_runtime.h>
#include <cuda_fp16.h>

#define BB 4
#define SS 1024
#define EE 1024
#define HH 16
#define DD 64
#define NQ 32
#define SCALE 0.125f
#define NBLK (BB * (SS / NQ))   // 128 fused blocks
#define NEGINF __int_as_float(0xff800000)

__device__ unsigned int g_bar;  // monotonic grid barrier (no reset needed)

// fused smem layout (bytes):
#define SMB_CTX    132096
#define SMB_KT     (SMB_CTX + 66048)     // 198144 (16B aligned)
#define SMB_Q16    (SMB_KT + 18432)      // 216576
#define SMB_KEEP   (SMB_Q16 + 4608)      // 221184
#define SMB_INV    (SMB_KEEP + 4096)     // 225280
#define FUSED_SMEM (SMB_INV + 128)       // 225408 <= 227KB

#define KV_SMEM (2 * 64 * 264 * 2)       // 67584
#define KTBUF 4608                        // halfs per 64-row buffer

__device__ __forceinline__ void mma16816(float c[4], const unsigned a[4],
                                         const unsigned bf[2]) {
    asm volatile(
        "mma.sync.aligned.m16n8k16.row.col.f32.f16.f16.f32 "
        "{%0,%1,%2,%3}, {%4,%5,%6,%7}, {%8,%9}, {%0,%1,%2,%3};\n"
        : "+f"(c[0]), "+f"(c[1]), "+f"(c[2]), "+f"(c[3])
        : "r"(a[0]), "r"(a[1]), "r"(a[2]), "r"(a[3]), "r"(bf[0]), "r"(bf[1]));
}

__device__ __forceinline__ unsigned su32(const void* p) {
    unsigned a;
    asm("{ .reg .u64 t; cvta.to.shared.u64 t, %1; cvt.u32.u64 %0, t; }"
        : "=r"(a) : "l"(p));
    return a;
}

__device__ __forceinline__ void cp16(unsigned dst, const void* src) {
    asm volatile("cp.async.ca.shared.global [%0], [%1], 16;\n"
                 :: "r"(dst), "l"(src));
}
#define CP_COMMIT() asm volatile("cp.async.commit_group;\n")
#define CP_WAIT0()  asm volatile("cp.async.wait_group 0;\n")
#define CP_WAIT1()  asm volatile("cp.async.wait_group 1;\n")

// canonical PV B-frag loader: V row-major [k][d], rows = k
__device__ __forceinline__ void ldmx2t(unsigned& r0, unsigned& r1, unsigned a) {
    asm volatile(
        "ldmatrix.sync.aligned.m8n8.x2.trans.shared.b16 {%0,%1}, [%2];\n"
        : "=r"(r0), "=r"(r1) : "r"(a));
}

// ============================================================================
// P1: K/V projection via HMMA -> fp16 into the (dead) output region.
// ============================================================================
__global__ void __launch_bounds__(256, 2)
kv_proj_kernel(const float* __restrict__ key,
               const float* __restrict__ value,
               const float* __restrict__ in_w,
               const float* __restrict__ in_b,
               __half* __restrict__ kv)
{
    extern __shared__ char sm[];
    __half* Xs = (__half*)sm;                  // [64][264]
    __half* Ws = Xs + 64 * 264;                // [64][264]

    const int which = blockIdx.x >> 4;         // 0=k, 1=v
    const int s0 = (blockIdx.x & 15) * 64;
    const int h = blockIdx.y, b = blockIdx.z;
    const float* X = (which ? value : key) + (size_t)b * SS * EE;
    const int woff = (which ? 2048 : 1024) + h * 64;

    const int tid = threadIdx.x;
    const int wid = tid >> 5, lane = tid & 31;
    const int g = lane >> 2, t = lane & 3;
    const int mw = (wid >> 1) * 16;
    const int nh = (wid & 1) * 32;

    float acc[4][4];
    #pragma unroll
    for (int i = 0; i < 4; i++)
        #pragma unroll
        for (int j = 0; j < 4; j++) acc[i][j] = 0.0f;

    for (int e0 = 0; e0 < 1024; e0 += 256) {
        __syncthreads();
        for (int i = tid; i < 4096; i += 256) {
            const int r = i >> 6, c4 = i & 63;
            float4 v = *(const float4*)&X[(size_t)(s0 + r) * 1024 + e0 + c4 * 4];
            *(__half2*)&Xs[r*264 + c4*4]     = __floats2half2_rn(v.x, v.y);
            *(__half2*)&Xs[r*264 + c4*4 + 2] = __floats2half2_rn(v.z, v.w);
        }
        for (int i = tid; i < 4096; i += 256) {
            const int r = i >> 6, c4 = i & 63;
            float4 v = *(const float4*)&in_w[(size_t)(woff + r) * 1024 + e0 + c4 * 4];
            *(__half2*)&Ws[r*264 + c4*4]     = __floats2half2_rn(v.x, v.y);
            *(__half2*)&Ws[r*264 + c4*4 + 2] = __floats2half2_rn(v.z, v.w);
        }
        __syncthreads();

        #pragma unroll
        for (int ks = 0; ks < 16; ks++) {
            const int k0 = ks * 16;
            unsigned a[4];
            a[0] = *(const unsigned*)&Xs[(mw+g)*264 + k0 + t*2];
            a[1] = *(const unsigned*)&Xs[(mw+g+8)*264 + k0 + t*2];
            a[2] = *(const unsigned*)&Xs[(mw+g)*264 + k0 + t*2 + 8];
            a[3] = *(const unsigned*)&Xs[(mw+g+8)*264 + k0 + t*2 + 8];
            #pragma unroll
            for (int ns = 0; ns < 4; ns++) {
                const int n = nh + ns * 8;
                unsigned bf[2];
                bf[0] = *(const unsigned*)&Ws[(n+g)*264 + k0 + t*2];
                bf[1] = *(const unsigned*)&Ws[(n+g)*264 + k0 + t*2 + 8];
                mma16816(acc[ns], a, bf);
            }
        }
    }

    __half* dst = kv + (size_t)which * (BB*HH*SS*DD)
                     + ((size_t)(b * HH + h) * SS) * DD;
    #pragma unroll
    for (int ns = 0; ns < 4; ns++) {
        const int n = nh + ns * 8;
        const float b0 = in_b[woff + n + t*2];
        const float b1 = in_b[woff + n + t*2 + 1];
        *(__half2*)&dst[(size_t)(s0+mw+g)*DD + n + t*2] =
            __floats2half2_rn(acc[ns][0] + b0, acc[ns][1] + b1);
        *(__half2*)&dst[(size_t)(s0+mw+g+8)*DD + n + t*2] =
            __floats2half2_rn(acc[ns][2] + b0, acc[ns][3] + b1);
    }
}

// ============================================================================
// P2: fused attention + out-projection; continuous 2-deep cp.async pipeline.
// ============================================================================
__global__ void __launch_bounds__(512, 1)
fused_attn_kernel(const float* __restrict__ query,
                  const float* __restrict__ in_w,
                  const float* __restrict__ in_b,
                  const unsigned int* __restrict__ mask_w,
                  const __half* __restrict__ kv,
                  const float* __restrict__ out_w,
                  const float* __restrict__ out_b,
                  float* __restrict__ mean_out,
                  float* __restrict__ out)
{
    extern __shared__ char smem[];
    float*  s_scores = (float*)smem;                 // [32][1032] f32
    __half* s_ctx    = (__half*)(smem + SMB_CTX);    // [32][1032] f16
    __half* s_kt     = (__half*)(smem + SMB_KT);     // [2][64][72] f16
    __half* s_q16    = (__half*)(smem + SMB_Q16);    // [32][72] f16
    float*  s_keep   = (float*)(smem + SMB_KEEP);
    float*  s_inv    = (float*)(smem + SMB_INV);

    const int qt = blockIdx.x, b = blockIdx.y;
    const int q0 = qt * NQ;
    const int tid = threadIdx.x;
    const int wid = tid >> 5, lane = tid & 31;
    const int g = lane >> 2, t = lane & 3;
    const int mw = (wid >> 3) * 16;   // 0|16
    const int nw = (wid & 7) * 8;     // 0..56
    const int str = tid >> 3;         // stage row 0..63
    const int stc = tid & 7;          // stage 16B chunk 0..7
    const unsigned stg0 = su32(&s_kt[str*72 + stc*8]);
    const unsigned stg1 = su32(&s_kt[KTBUF + str*72 + stc*8]);

    for (int i = tid; i < 1024; i += 512)
        s_keep[i] = (mask_w[b * SS + i] != 0u) ? 1.0f : 0.0f;

    // pipeline prologue: K tiles 0,1 of head 0
    {
        const __half* Kb0 = kv + ((size_t)(b * HH) * SS) * DD;
        cp16(stg0, &Kb0[(size_t)str*64 + stc*8]);            CP_COMMIT();
        cp16(stg1, &Kb0[(size_t)(64 + str)*64 + stc*8]);     CP_COMMIT();
    }

    for (int h = 0; h < HH; h++) {
        const __half* Kb = kv + ((size_t)(b * HH + h) * SS) * DD;
        const __half* Vb = Kb + (size_t)(BB*HH*SS*DD);

        // ---------- Q-proj (mma, dual acc); K0/K1 loads fly underneath ----------
        {
            __half* qst = (__half*)smem;          // [32][264]
            __half* wst = qst + 32 * 264;         // [64][264]
            float qc0[4] = {0.f,0.f,0.f,0.f}, qc1[4] = {0.f,0.f,0.f,0.f};

            for (int e0 = 0; e0 < 1024; e0 += 256) {
                __syncthreads();
                for (int i = tid; i < 2048; i += 512) {
                    const int r = i >> 6, c4 = i & 63;
                    float4 v = *(const float4*)&query[((size_t)(b*SS)+q0+r)*1024 + e0 + c4*4];
                    *(__half2*)&qst[r*264 + c4*4]     = __floats2half2_rn(v.x, v.y);
                    *(__half2*)&qst[r*264 + c4*4 + 2] = __floats2half2_rn(v.z, v.w);
                }
                for (int i = tid; i < 4096; i += 512) {
                    const int r = i >> 6, c4 = i & 63;
                    float4 v = *(const float4*)&in_w[(size_t)(h*64+r)*1024 + e0 + c4*4];
                    *(__half2*)&wst[r*264 + c4*4]     = __floats2half2_rn(v.x, v.y);
                    *(__half2*)&wst[r*264 + c4*4 + 2] = __floats2half2_rn(v.z, v.w);
                }
                __syncthreads();

                #pragma unroll
                for (int ks = 0; ks < 16; ks++) {
                    const int k0 = ks * 16;
                    unsigned a[4], bf[2];
                    a[0] = *(const unsigned*)&qst[(mw+g)*264 + k0 + t*2];
                    a[1] = *(const unsigned*)&qst[(mw+g+8)*264 + k0 + t*2];
                    a[2] = *(const unsigned*)&qst[(mw+g)*264 + k0 + t*2 + 8];
                    a[3] = *(const unsigned*)&qst[(mw+g+8)*264 + k0 + t*2 + 8];
                    bf[0] = *(const unsigned*)&wst[(nw+g)*264 + k0 + t*2];
                    bf[1] = *(const unsigned*)&wst[(nw+g)*264 + k0 + t*2 + 8];
                    if (ks & 1) mma16816(qc1, a, bf);
                    else        mma16816(qc0, a, bf);
                }
            }
            const float bb0 = in_b[h*64 + nw + t*2];
            const float bb1 = in_b[h*64 + nw + t*2 + 1];
            *(__half2*)&s_q16[(mw+g)*72 + nw + t*2] =
                __floats2half2_rn(qc0[0]+qc1[0]+bb0, qc0[1]+qc1[1]+bb1);
            *(__half2*)&s_q16[(mw+g+8)*72 + nw + t*2] =
                __floats2half2_rn(qc0[2]+qc1[2]+bb0, qc0[3]+qc1[3]+bb1);
        }
        __syncthreads();

        // hoisted A-frags (Q): same for all k-tiles
        unsigned aq[4][4];
        #pragma unroll
        for (int ks = 0; ks < 4; ks++) {
            const int k0 = ks * 16;
            aq[ks][0] = *(const unsigned*)&s_q16[(mw+g)*72 + k0 + t*2];
            aq[ks][1] = *(const unsigned*)&s_q16[(mw+g+8)*72 + k0 + t*2];
            aq[ks][2] = *(const unsigned*)&s_q16[(mw+g)*72 + k0 + t*2 + 8];
            aq[ks][3] = *(const unsigned*)&s_q16[(mw+g+8)*72 + k0 + t*2 + 8];
        }

        // ---------- scores: pipelined (tile kt ready, kt+1 in flight) ----------
        for (int kt = 0; kt < 16; kt++) {
            CP_WAIT1();
            __syncthreads();
            const int buf = (kt & 1) * KTBUF;

            float sc0[4] = {0.f,0.f,0.f,0.f}, sc1[4] = {0.f,0.f,0.f,0.f};
            #pragma unroll
            for (int ks = 0; ks < 4; ks++) {
                const int k0 = ks * 16;
                unsigned bf[2];
                bf[0] = *(const unsigned*)&s_kt[buf + (nw+g)*72 + k0 + t*2];
                bf[1] = *(const unsigned*)&s_kt[buf + (nw+g)*72 + k0 + t*2 + 8];
                if (ks & 1) mma16816(sc1, aq[ks], bf);
                else        mma16816(sc0, aq[ks], bf);
            }

            const int kg = kt*64 + nw + t*2;
            const float kf0 = s_keep[kg], kf1 = s_keep[kg+1];
            const int r0 = mw + g, r1 = mw + g + 8;
            float v00 = (sc0[0]+sc1[0])*SCALE + (float)(q0 + r0 - kg);
            float v01 = (sc0[1]+sc1[1])*SCALE + (float)(q0 + r0 - kg - 1);
            float v10 = (sc0[2]+sc1[2])*SCALE + (float)(q0 + r1 - kg);
            float v11 = (sc0[3]+sc1[3])*SCALE + (float)(q0 + r1 - kg - 1);
            v00 = (kf0 != 0.f) ? v00 : NEGINF;
            v01 = (kf1 != 0.f) ? v01 : NEGINF;
            v10 = (kf0 != 0.f) ? v10 : NEGINF;
            v11 = (kf1 != 0.f) ? v11 : NEGINF;
            *(float2*)&s_scores[r0*1032 + kg] = make_float2(v00, v01);
            *(float2*)&s_scores[r1*1032 + kg] = make_float2(v10, v11);

            __syncthreads();     // all warps done with buf before overwrite
            const unsigned dst = (kt & 1) ? stg1 : stg0;
            if (kt + 2 < 16) {
                cp16(dst, &Kb[(size_t)((kt+2)*64 + str)*64 + stc*8]); CP_COMMIT();
            } else if (kt == 14) {   // V0 -> buf0 (hidden under softmax)
                cp16(stg0, &Vb[(size_t)str*64 + stc*8]); CP_COMMIT();
            } else {                 // kt==15: V1 -> buf1
                cp16(stg1, &Vb[(size_t)(64 + str)*64 + stc*8]); CP_COMMIT();
            }
        }

        // ---------- softmax (warp/row); P~ fp16 in place; mean from regs ----------
        for (int r = wid; r < 32; r += 16) {
            float* srow = s_scores + r * 1032;
            __half* prow = (__half*)srow;

            float mx = NEGINF;
            #pragma unroll
            for (int i = 0; i < 32; i++) mx = fmaxf(mx, srow[lane + 32*i]);
            #pragma unroll
            for (int m = 16; m >= 1; m >>= 1)
                mx = fmaxf(mx, __shfl_xor_sync(0xffffffffu, mx, m));

            float pv[32];
            float sum = 0.f;
            #pragma unroll
            for (int i = 0; i < 32; i++) {
                const float p = __expf(srow[lane + 32*i] - mx);
                pv[i] = p; sum += p;
            }
            #pragma unroll
            for (int m = 16; m >= 1; m >>= 1)
                sum += __shfl_xor_sync(0xffffffffu, sum, m);

            const float inv = 1.0f / sum;
            if (lane == 0) s_inv[r] = inv;

            #pragma unroll
            for (int i = 0; i < 32; i++)
                prow[lane + 32*i] = __float2half(pv[i]);

            float* mrow = mean_out + ((size_t)(b*SS) + q0 + r) * SS;
            const float msc = inv * 0.0625f;
            if (h == 0) {
                #pragma unroll
                for (int i = 0; i < 32; i++) mrow[lane + 32*i] = pv[i] * msc;
            } else {
                #pragma unroll
                for (int i = 0; i < 32; i++) mrow[lane + 32*i] += pv[i] * msc;
            }
        }

        // ---------- PV: pipelined; tail prefetches next head's K ----------
        {
            float ca0[4] = {0.f,0.f,0.f,0.f}, ca1[4] = {0.f,0.f,0.f,0.f};
            const char* pbase = (const char*)s_scores + (size_t)(mw+g)*4128;
            const char* pbase8 = (const char*)s_scores + (size_t)(mw+g+8)*4128;

            for (int kt = 0; kt < 16; kt++) {
                if (kt == 15 && h == HH-1) CP_WAIT0(); else CP_WAIT1();
                __syncthreads();
                const int buf = (kt & 1) * KTBUF;

                #pragma unroll
                for (int ks = 0; ks < 4; ks++) {
                    const int kk = kt*64 + ks*16 + t*2;
                    unsigned a[4], bf[2];
                    a[0] = *(const unsigned*)(pbase + kk*2);
                    a[1] = *(const unsigned*)(pbase8 + kk*2);
                    a[2] = *(const unsigned*)(pbase + (kk+8)*2);
                    a[3] = *(const unsigned*)(pbase8 + (kk+8)*2);
                    const int krow = ks*16 + (lane & 15);
                    ldmx2t(bf[0], bf[1], su32(&s_kt[buf + krow*72 + nw]));
                    if (ks & 1) mma16816(ca1, a, bf);
                    else        mma16816(ca0, a, bf);
                }

                __syncthreads();
                const unsigned dst = (kt & 1) ? stg1 : stg0;
                if (kt + 2 < 16) {
                    cp16(dst, &Vb[(size_t)((kt+2)*64 + str)*64 + stc*8]); CP_COMMIT();
                } else if (h + 1 < HH) {
                    const __half* Kbn = Kb + (size_t)SS * DD;   // next head's K
                    if (kt == 14) { cp16(stg0, &Kbn[(size_t)str*64 + stc*8]); CP_COMMIT(); }
                    else          { cp16(stg1, &Kbn[(size_t)(64 + str)*64 + stc*8]); CP_COMMIT(); }
                }
            }

            const int r0 = mw + g, r1 = mw + g + 8;
            const float i0 = s_inv[r0], i1 = s_inv[r1];
            *(__half2*)&s_ctx[r0*1032 + h*64 + nw + t*2] =
                __floats2half2_rn((ca0[0]+ca1[0])*i0, (ca0[1]+ca1[1])*i0);
            *(__half2*)&s_ctx[r1*1032 + h*64 + nw + t*2] =
                __floats2half2_rn((ca0[2]+ca1[2])*i1, (ca0[3]+ca1[3])*i1);
        }
        __syncthreads();
    }

    // ==================== grid barrier ====================
    if (tid == 0) {
        __threadfence();
        const unsigned int old = atomicAdd(&g_bar, 1u);
        const unsigned int target = (old / NBLK + 1u) * NBLK;
        while (atomicAdd(&g_bar, 0u) < target) { }
    }
    __syncthreads();

    // ==================== out-proj (mma, dual acc): out = ctx @ Wo^T + bias ====
    {
        __half* woS = (__half*)smem;              // [64][1032] fp16 (scores dead)
        for (int n0 = 0; n0 < 1024; n0 += 64) {
            __syncthreads();
            for (int i = tid; i < 16384; i += 512) {
                const int r = i >> 8, c4 = i & 255;
                float4 v = *(const float4*)&out_w[(size_t)(n0 + r)*1024 + c4*4];
                *(__half2*)&woS[r*1032 + c4*4]     = __floats2half2_rn(v.x, v.y);
                *(__half2*)&woS[r*1032 + c4*4 + 2] = __floats2half2_rn(v.z, v.w);
            }
            __syncthreads();

            float oc0[4] = {0.f,0.f,0.f,0.f}, oc1[4] = {0.f,0.f,0.f,0.f};
            #pragma unroll 8
            for (int ks = 0; ks < 64; ks++) {
                const int k0 = ks * 16;
                unsigned a[4], bf[2];
                a[0] = *(const unsigned*)&s_ctx[(mw+g)*1032 + k0 + t*2];
                a[1] = *(const unsigned*)&s_ctx[(mw+g+8)*1032 + k0 + t*2];
                a[2] = *(const unsigned*)&s_ctx[(mw+g)*1032 + k0 + t*2 + 8];
                a[3] = *(const unsigned*)&s_ctx[(mw+g+8)*1032 + k0 + t*2 + 8];
                bf[0] = *(const unsigned*)&woS[(nw+g)*1032 + k0 + t*2];
                bf[1] = *(const unsigned*)&woS[(nw+g)*1032 + k0 + t*2 + 8];
                if (ks & 1) mma16816(oc1, a, bf);
                else        mma16816(oc0, a, bf);
            }

            const int col = n0 + nw + t*2;
            const float bb0 = out_b[col], bb1 = out_b[col+1];
            const int r0 = mw + g, r1 = mw + g + 8;
            *(float2*)&out[((size_t)(b*SS)+q0+r0)*1024 + col] =
                make_float2(oc0[0]+oc1[0]+bb0, oc0[1]+oc1[1]+bb1);
            *(float2*)&out[((size_t)(b*SS)+q0+r1)*1024 + col] =
                make_float2(oc0[2]+oc1[2]+bb0, oc0[3]+oc1[3]+bb1);
        }
    }
}

// ============================================================================
extern "C" void kernel_launch(void* const* d_in, const int* in_sizes, int n_in,
                              void* d_out, int out_size)
{
    const float* query = (const float*)d_in[0];
    const float* key   = (const float*)d_in[1];
    const float* value = (const float*)d_in[2];
    const unsigned int* mask_w = (const unsigned int*)d_in[3];
    const float* in_w  = (const float*)d_in[4];
    const float* in_b  = (const float*)d_in[5];
    const float* out_w = (const float*)d_in[6];
    const float* out_b = (const float*)d_in[7];

    float* out      = (float*)d_out;                 // (B,S,E); kv fp16 until out-proj
    float* mean_out = out + (size_t)BB * SS * EE;    // (B,S,S)
    __half* kv      = (__half*)d_out;

    cudaFuncSetAttribute(fused_attn_kernel,
                         cudaFuncAttributeMaxDynamicSharedMemorySize, FUSED_SMEM);
    cudaFuncSetAttribute(kv_proj_kernel,
                         cudaFuncAttributeMaxDynamicSharedMemorySize, KV_SMEM);

    kv_proj_kernel<<<dim3(32, HH, BB), 256, KV_SMEM>>>(key, value, in_w, in_b, kv);

    fused_attn_kernel<<<dim3(SS / NQ, BB), 512, FUSED_SMEM>>>(
        query, in_w, in_b, mask_w, kv, out_w, out_b, mean_out, out);
}

// round 16
// speedup vs baseline: 5.8965x; 1.0866x over previous
#include <cuda_runtime.h>
#include <cuda_fp16.h>

#define BB 4
#define SS 1024
#define EE 1024
#define HH 16
#define DD 64
#define NQ 32
#define SCALE 0.125f
#define NBLK (BB * (SS / NQ))   // 128 fused blocks
#define NEGINF __int_as_float(0xff800000)

__device__ unsigned int g_bar;  // monotonic grid barrier (no reset needed)

// fused smem layout (bytes):
#define SMB_CTX    132096                // s_scores f32 [32][1032] before it
#define SMB_KT     (SMB_CTX + 66048)     // 198144 (16B aligned)
#define SMB_KEEP   (SMB_KT + 18432)      // 216576
#define SMB_INV    (SMB_KEEP + 4096)     // 220672
#define FUSED_SMEM (SMB_INV + 128)       // 220800 <= 227KB

#define KV_SMEM (2 * 64 * 264 * 2)       // 67584
#define KTBUF 4608                        // halfs per 64-row buffer

__device__ __forceinline__ void mma16816(float c[4], const unsigned a[4],
                                         const unsigned bf[2]) {
    asm volatile(
        "mma.sync.aligned.m16n8k16.row.col.f32.f16.f16.f32 "
        "{%0,%1,%2,%3}, {%4,%5,%6,%7}, {%8,%9}, {%0,%1,%2,%3};\n"
        : "+f"(c[0]), "+f"(c[1]), "+f"(c[2]), "+f"(c[3])
        : "r"(a[0]), "r"(a[1]), "r"(a[2]), "r"(a[3]), "r"(bf[0]), "r"(bf[1]));
}

__device__ __forceinline__ unsigned su32(const void* p) {
    unsigned a;
    asm("{ .reg .u64 t; cvta.to.shared.u64 t, %1; cvt.u32.u64 %0, t; }"
        : "=r"(a) : "l"(p));
    return a;
}

__device__ __forceinline__ void cp16(unsigned dst, const void* src) {
    asm volatile("cp.async.ca.shared.global [%0], [%1], 16;\n"
                 :: "r"(dst), "l"(src));
}
#define CP_COMMIT() asm volatile("cp.async.commit_group;\n")
#define CP_WAIT0()  asm volatile("cp.async.wait_group 0;\n")
#define CP_WAIT1()  asm volatile("cp.async.wait_group 1;\n")

__device__ __forceinline__ void ldmx4(unsigned r[4], unsigned a) {
    asm volatile("ldmatrix.sync.aligned.m8n8.x4.shared.b16 {%0,%1,%2,%3}, [%4];\n"
        : "=r"(r[0]), "=r"(r[1]), "=r"(r[2]), "=r"(r[3]) : "r"(a));
}
__device__ __forceinline__ void ldmx4t(unsigned r[4], unsigned a) {
    asm volatile("ldmatrix.sync.aligned.m8n8.x4.trans.shared.b16 {%0,%1,%2,%3}, [%4];\n"
        : "=r"(r[0]), "=r"(r[1]), "=r"(r[2]), "=r"(r[3]) : "r"(a));
}

// ============================================================================
// P1: K/V projection via HMMA -> fp16 into the (dead) output region.
// ============================================================================
__global__ void __launch_bounds__(256, 2)
kv_proj_kernel(const float* __restrict__ key,
               const float* __restrict__ value,
               const float* __restrict__ in_w,
               const float* __restrict__ in_b,
               __half* __restrict__ kv)
{
    extern __shared__ char sm[];
    __half* Xs = (__half*)sm;                  // [64][264]
    __half* Ws = Xs + 64 * 264;                // [64][264]

    const int which = blockIdx.x >> 4;         // 0=k, 1=v
    const int s0 = (blockIdx.x & 15) * 64;
    const int h = blockIdx.y, b = blockIdx.z;
    const float* X = (which ? value : key) + (size_t)b * SS * EE;
    const int woff = (which ? 2048 : 1024) + h * 64;

    const int tid = threadIdx.x;
    const int wid = tid >> 5, lane = tid & 31;
    const int g = lane >> 2, t = lane & 3;
    const int mw = (wid >> 1) * 16;
    const int nh = (wid & 1) * 32;

    float acc[4][4];
    #pragma unroll
    for (int i = 0; i < 4; i++)
        #pragma unroll
        for (int j = 0; j < 4; j++) acc[i][j] = 0.0f;

    const unsigned aB = su32(Xs) + (mw + (lane & 15))*528 + ((lane & 16) ? 16 : 0);
    const unsigned bB0 = su32(Ws) + (nh + (lane & 7))*528
                         + (((lane >> 3) & 1) ? 16 : 0)
                         + ((lane & 16) ? 528*8 : 0);
    const unsigned bB1 = bB0 + 16*528;

    for (int e0 = 0; e0 < 1024; e0 += 256) {
        __syncthreads();
        for (int i = tid; i < 4096; i += 256) {
            const int r = i >> 6, c4 = i & 63;
            float4 v = *(const float4*)&X[(size_t)(s0 + r) * 1024 + e0 + c4 * 4];
            *(__half2*)&Xs[r*264 + c4*4]     = __floats2half2_rn(v.x, v.y);
            *(__half2*)&Xs[r*264 + c4*4 + 2] = __floats2half2_rn(v.z, v.w);
        }
        for (int i = tid; i < 4096; i += 256) {
            const int r = i >> 6, c4 = i & 63;
            float4 v = *(const float4*)&in_w[(size_t)(woff + r) * 1024 + e0 + c4 * 4];
            *(__half2*)&Ws[r*264 + c4*4]     = __floats2half2_rn(v.x, v.y);
            *(__half2*)&Ws[r*264 + c4*4 + 2] = __floats2half2_rn(v.z, v.w);
        }
        __syncthreads();

        #pragma unroll
        for (int ks = 0; ks < 16; ks++) {
            unsigned a[4];
            ldmx4(a, aB + ks*32);
            unsigned bb[4];
            ldmx4(bb, bB0 + ks*32);              // n tiles nh, nh+8
            mma16816(acc[0], a, bb);
            mma16816(acc[1], a, bb + 2);
            ldmx4(bb, bB1 + ks*32);              // n tiles nh+16, nh+24
            mma16816(acc[2], a, bb);
            mma16816(acc[3], a, bb + 2);
        }
    }

    __half* dst = kv + (size_t)which * (BB*HH*SS*DD)
                     + ((size_t)(b * HH + h) * SS) * DD;
    #pragma unroll
    for (int ns = 0; ns < 4; ns++) {
        const int n = nh + ns * 8;
        const float b0 = in_b[woff + n + t*2];
        const float b1 = in_b[woff + n + t*2 + 1];
        *(__half2*)&dst[(size_t)(s0+mw+g)*DD + n + t*2] =
            __floats2half2_rn(acc[ns][0] + b0, acc[ns][1] + b1);
        *(__half2*)&dst[(size_t)(s0+mw+g+8)*DD + n + t*2] =
            __floats2half2_rn(acc[ns][2] + b0, acc[ns][3] + b1);
    }
}

// ============================================================================
// P2: fused attention + out-projection; ldmatrix.x4 + hoisted Q-proj.
// ============================================================================
__global__ void __launch_bounds__(512, 1)
fused_attn_kernel(const float* __restrict__ query,
                  const float* __restrict__ in_w,
                  const float* __restrict__ in_b,
                  const unsigned int* __restrict__ mask_w,
                  const __half* __restrict__ kv,
                  const float* __restrict__ out_w,
                  const float* __restrict__ out_b,
                  float* __restrict__ mean_out,
                  float* __restrict__ out)
{
    extern __shared__ char smem[];
    float*  s_scores = (float*)smem;                 // [32][1032] f32
    __half* s_ctx    = (__half*)(smem + SMB_CTX);    // [32][1032] f16: q16all -> ctx
    __half* s_kt     = (__half*)(smem + SMB_KT);     // [2][64][72] f16
    float*  s_keep   = (float*)(smem + SMB_KEEP);
    float*  s_inv    = (float*)(smem + SMB_INV);

    const int qt = blockIdx.x, b = blockIdx.y;
    const int q0 = qt * NQ;
    const int tid = threadIdx.x;
    const int wid = tid >> 5, lane = tid & 31;
    const int g = lane >> 2, t = lane & 3;
    const int mw = (wid >> 3) * 16;   // 0|16
    const int nw = (wid & 7) * 8;     // 0..56
    const int str = tid >> 3;         // stage row 0..63
    const int stc = tid & 7;          // stage 16B chunk 0..7
    const unsigned stg0 = su32(&s_kt[str*72 + stc*8]);
    const unsigned stg1 = su32(&s_kt[KTBUF + str*72 + stc*8]);

    // ldmatrix per-thread bases
    const int lane15 = lane & 15, lane7 = lane & 7;
    const unsigned cxA = su32(s_ctx) + (mw + lane15)*2064 + ((lane & 16) ? 16 : 0);
    const unsigned pA  = su32(s_scores) + (mw + lane15)*4128 + ((lane & 16) ? 16 : 0);
    const unsigned kB0 = su32(s_kt) + (nw + lane7)*144 + ((lane >> 3) & 3)*16;
    const unsigned kB1 = kB0 + KTBUF*2;
    const unsigned vT0 = su32(s_kt) + lane*144 + nw*2;
    const unsigned vT1 = vT0 + KTBUF*2;

    for (int i = tid; i < 1024; i += 512)
        s_keep[i] = (mask_w[b * SS + i] != 0u) ? 1.0f : 0.0f;

    // pipeline prologue: K tiles 0,1 of head 0 (fly under the big Q-proj)
    {
        const __half* Kb0 = kv + ((size_t)(b * HH) * SS) * DD;
        cp16(stg0, &Kb0[(size_t)str*64 + stc*8]);            CP_COMMIT();
        cp16(stg1, &Kb0[(size_t)(64 + str)*64 + stc*8]);     CP_COMMIT();
    }

    // ======== upfront Q-proj for ALL heads -> s_ctx.
    // Staging strictly inside scores region [0, 132096): q16a 0..66048,
    // wst [64][264] 66048..99840. NO overlap with s_ctx (132096..198144).
    {
        __half* q16a = (__half*)smem;            // [32][1032]
        __half* wst  = (__half*)(smem + 66048);  // [64][264] per-k0 chunk
        for (int i = tid; i < 8192; i += 512) {
            const int r = i >> 8, c4 = i & 255;
            float4 v = *(const float4*)&query[((size_t)(b*SS)+q0+r)*1024 + c4*4];
            *(__half2*)&q16a[r*1032 + c4*4]     = __floats2half2_rn(v.x, v.y);
            *(__half2*)&q16a[r*1032 + c4*4 + 2] = __floats2half2_rn(v.z, v.w);
        }
        __syncthreads();

        const unsigned qA = su32(q16a) + (mw + lane15)*2064 + ((lane & 16) ? 16 : 0);
        const unsigned wB = su32(wst) + (nw + lane7)*528 + ((lane >> 3) & 3)*16;

        for (int n0 = 0; n0 < 1024; n0 += 64) {
            float qc0[4] = {0.f,0.f,0.f,0.f}, qc1[4] = {0.f,0.f,0.f,0.f};

            for (int k0 = 0; k0 < 1024; k0 += 256) {
                __syncthreads();
                for (int i = tid; i < 4096; i += 512) {
                    const int r = i >> 6, c4 = i & 63;
                    float4 v = *(const float4*)&in_w[(size_t)(n0 + r)*1024 + k0 + c4*4];
                    *(__half2*)&wst[r*264 + c4*4]     = __floats2half2_rn(v.x, v.y);
                    *(__half2*)&wst[r*264 + c4*4 + 2] = __floats2half2_rn(v.z, v.w);
                }
                __syncthreads();

                #pragma unroll
                for (int ks2 = 0; ks2 < 8; ks2++) {
                    unsigned aa[4], ab[4], bb[4];
                    ldmx4(aa, qA + k0*2 + ks2*64);
                    ldmx4(ab, qA + k0*2 + ks2*64 + 32);
                    ldmx4(bb, wB + ks2*64);
                    mma16816(qc0, aa, bb);
                    mma16816(qc1, ab, bb + 2);
                }
            }
            const int col = n0 + nw + t*2;
            const float bb0 = in_b[col], bb1 = in_b[col+1];
            *(__half2*)&s_ctx[(mw+g)*1032 + col] =
                __floats2half2_rn(qc0[0]+qc1[0]+bb0, qc0[1]+qc1[1]+bb1);
            *(__half2*)&s_ctx[(mw+g+8)*1032 + col] =
                __floats2half2_rn(qc0[2]+qc1[2]+bb0, qc0[3]+qc1[3]+bb1);
        }
        __syncthreads();   // q16all visible to all warps before head loop
    }

    for (int h = 0; h < HH; h++) {
        const __half* Kb = kv + ((size_t)(b * HH + h) * SS) * DD;
        const __half* Vb = Kb + (size_t)(BB*HH*SS*DD);

        // hoisted A-frags (Q of head h) from s_ctx cols h*64
        unsigned aq[4][4];
        #pragma unroll
        for (int ks = 0; ks < 4; ks++)
            ldmx4(aq[ks], cxA + h*128 + ks*32);

        // ---------- scores: pipelined; 2 ldmatrix + 4 mma per k-tile ----------
        for (int kt = 0; kt < 16; kt++) {
            CP_WAIT1();
            __syncthreads();
            const unsigned kB = (kt & 1) ? kB1 : kB0;

            float sc0[4] = {0.f,0.f,0.f,0.f}, sc1[4] = {0.f,0.f,0.f,0.f};
            unsigned bb[4];
            ldmx4(bb, kB);
            mma16816(sc0, aq[0], bb);
            mma16816(sc1, aq[1], bb + 2);
            ldmx4(bb, kB + 64);
            mma16816(sc0, aq[2], bb);
            mma16816(sc1, aq[3], bb + 2);

            __syncthreads();     // all warps done with buf before overwrite
            const unsigned dst = (kt & 1) ? stg1 : stg0;
            if (kt + 2 < 16) {
                cp16(dst, &Kb[(size_t)((kt+2)*64 + str)*64 + stc*8]); CP_COMMIT();
            } else if (kt == 14) {
                cp16(stg0, &Vb[(size_t)str*64 + stc*8]); CP_COMMIT();
            } else {
                cp16(stg1, &Vb[(size_t)(64 + str)*64 + stc*8]); CP_COMMIT();
            }

            // epilogue (no s_kt dependency) overlaps the prefetch flight
            const int kg = kt*64 + nw + t*2;
            const float kf0 = s_keep[kg], kf1 = s_keep[kg+1];
            const int r0 = mw + g, r1 = mw + g + 8;
            float v00 = (sc0[0]+sc1[0])*SCALE + (float)(q0 + r0 - kg);
            float v01 = (sc0[1]+sc1[1])*SCALE + (float)(q0 + r0 - kg - 1);
            float v10 = (sc0[2]+sc1[2])*SCALE + (float)(q0 + r1 - kg);
            float v11 = (sc0[3]+sc1[3])*SCALE + (float)(q0 + r1 - kg - 1);
            v00 = (kf0 != 0.f) ? v00 : NEGINF;
            v01 = (kf1 != 0.f) ? v01 : NEGINF;
            v10 = (kf0 != 0.f) ? v10 : NEGINF;
            v11 = (kf1 != 0.f) ? v11 : NEGINF;
            *(float2*)&s_scores[r0*1032 + kg] = make_float2(v00, v01);
            *(float2*)&s_scores[r1*1032 + kg] = make_float2(v10, v11);
        }
        __syncthreads();   // epilogue visible to softmax

        // ---------- softmax (warp/row, single smem read) ----------
        for (int r = wid; r < 32; r += 16) {
            float* srow = s_scores + r * 1032;
            __half* prow = (__half*)srow;

            float pvv[32];
            #pragma unroll
            for (int i = 0; i < 32; i++) pvv[i] = srow[lane + 32*i];

            float mx = NEGINF;
            #pragma unroll
            for (int i = 0; i < 32; i++) mx = fmaxf(mx, pvv[i]);
            #pragma unroll
            for (int m = 16; m >= 1; m >>= 1)
                mx = fmaxf(mx, __shfl_xor_sync(0xffffffffu, mx, m));

            float sum = 0.f;
            #pragma unroll
            for (int i = 0; i < 32; i++) {
                const float p = __expf(pvv[i] - mx);
                pvv[i] = p; sum += p;
            }
            #pragma unroll
            for (int m = 16; m >= 1; m >>= 1)
                sum += __shfl_xor_sync(0xffffffffu, sum, m);

            const float inv = 1.0f / sum;
            if (lane == 0) s_inv[r] = inv;

            #pragma unroll
            for (int i = 0; i < 32; i++)
                prow[lane + 32*i] = __float2half(pvv[i]);

            float* mrow = mean_out + ((size_t)(b*SS) + q0 + r) * SS;
            const float msc = inv * 0.0625f;
            if (h == 0) {
                #pragma unroll
                for (int i = 0; i < 32; i++) mrow[lane + 32*i] = pvv[i] * msc;
            } else {
                #pragma unroll
                for (int i = 0; i < 32; i++) mrow[lane + 32*i] += pvv[i] * msc;
            }
        }

        // ---------- PV: pipelined; 6 ldmatrix + 4 mma per k-tile ----------
        {
            float ca0[4] = {0.f,0.f,0.f,0.f}, ca1[4] = {0.f,0.f,0.f,0.f};

            for (int kt = 0; kt < 16; kt++) {
                if (kt == 15 && h == HH-1) CP_WAIT0(); else CP_WAIT1();
                __syncthreads();
                const unsigned vT = (kt & 1) ? vT1 : vT0;
                const unsigned pa = pA + kt*128;

                unsigned a0[4], a1[4], a2[4], a3[4], b0[4], b1[4];
                ldmx4(a0, pa);
                ldmx4(a1, pa + 32);
                ldmx4(a2, pa + 64);
                ldmx4(a3, pa + 96);
                ldmx4t(b0, vT);
                ldmx4t(b1, vT + 32*144);
                mma16816(ca0, a0, b0);
                mma16816(ca1, a1, b0 + 2);
                mma16816(ca0, a2, b1);
                mma16816(ca1, a3, b1 + 2);

                __syncthreads();
                const unsigned dst = (kt & 1) ? stg1 : stg0;
                if (kt + 2 < 16) {
                    cp16(dst, &Vb[(size_t)((kt+2)*64 + str)*64 + stc*8]); CP_COMMIT();
                } else if (h + 1 < HH) {
                    const __half* Kbn = Kb + (size_t)SS * DD;   // next head's K
                    if (kt == 14) { cp16(stg0, &Kbn[(size_t)str*64 + stc*8]); CP_COMMIT(); }
                    else          { cp16(stg1, &Kbn[(size_t)(64 + str)*64 + stc*8]); CP_COMMIT(); }
                }
            }

            const int r0 = mw + g, r1 = mw + g + 8;
            const float i0 = s_inv[r0], i1 = s_inv[r1];
            *(__half2*)&s_ctx[r0*1032 + h*64 + nw + t*2] =
                __floats2half2_rn((ca0[0]+ca1[0])*i0, (ca0[1]+ca1[1])*i0);
            *(__half2*)&s_ctx[r1*1032 + h*64 + nw + t*2] =
                __floats2half2_rn((ca0[2]+ca1[2])*i1, (ca0[3]+ca1[3])*i1);
        }
        __syncthreads();
    }

    // ==================== grid barrier ====================
    if (tid == 0) {
        __threadfence();
        const unsigned int old = atomicAdd(&g_bar, 1u);
        const unsigned int target = (old / NBLK + 1u) * NBLK;
        while (atomicAdd(&g_bar, 0u) < target) { }
    }
    __syncthreads();

    // ==================== out-proj: out = ctx @ Wo^T + bias ====================
    {
        __half* woS = (__half*)smem;              // [64][1032] fp16 (scores dead)
        const unsigned wB = su32(woS) + (nw + lane7)*2064 + ((lane >> 3) & 3)*16;

        for (int n0 = 0; n0 < 1024; n0 += 64) {
            __syncthreads();
            for (int i = tid; i < 16384; i += 512) {
                const int r = i >> 8, c4 = i & 255;
                float4 v = *(const float4*)&out_w[(size_t)(n0 + r)*1024 + c4*4];
                *(__half2*)&woS[r*1032 + c4*4]     = __floats2half2_rn(v.x, v.y);
                *(__half2*)&woS[r*1032 + c4*4 + 2] = __floats2half2_rn(v.z, v.w);
            }
            __syncthreads();

            float oc0[4] = {0.f,0.f,0.f,0.f}, oc1[4] = {0.f,0.f,0.f,0.f};
            #pragma unroll 4
            for (int ks2 = 0; ks2 < 32; ks2++) {
                unsigned aa[4], ab[4], bb[4];
                ldmx4(aa, cxA + ks2*64);
                ldmx4(ab, cxA + ks2*64 + 32);
                ldmx4(bb, wB + ks2*64);
                mma16816(oc0, aa, bb);
                mma16816(oc1, ab, bb + 2);
            }

            const int col = n0 + nw + t*2;
            const float bb0 = out_b[col], bb1 = out_b[col+1];
            const int r0 = mw + g, r1 = mw + g + 8;
            *(float2*)&out[((size_t)(b*SS)+q0+r0)*1024 + col] =
                make_float2(oc0[0]+oc1[0]+bb0, oc0[1]+oc1[1]+bb1);
            *(float2*)&out[((size_t)(b*SS)+q0+r1)*1024 + col] =
                make_float2(oc0[2]+oc1[2]+bb0, oc0[3]+oc1[3]+bb1);
        }
    }
}

// ============================================================================
extern "C" void kernel_launch(void* const* d_in, const int* in_sizes, int n_in,
                              void* d_out, int out_size)
{
    const float* query = (const float*)d_in[0];
    const float* key   = (const float*)d_in[1];
    const float* value = (const float*)d_in[2];
    const unsigned int* mask_w = (const unsigned int*)d_in[3];
    const float* in_w  = (const float*)d_in[4];
    const float* in_b  = (const float*)d_in[5];
    const float* out_w = (const float*)d_in[6];
    const float* out_b = (const float*)d_in[7];

    float* out      = (float*)d_out;                 // (B,S,E); kv fp16 until out-proj
    float* mean_out = out + (size_t)BB * SS * EE;    // (B,S,S)
    __half* kv      = (__half*)d_out;

    cudaFuncSetAttribute(fused_attn_kernel,
                         cudaFuncAttributeMaxDynamicSharedMemorySize, FUSED_SMEM);
    cudaFuncSetAttribute(kv_proj_kernel,
                         cudaFuncAttributeMaxDynamicSharedMemorySize, KV_SMEM);

    kv_proj_kernel<<<dim3(32, HH, BB), 256, KV_SMEM>>>(key, value, in_w, in_b, kv);

    fused_attn_kernel<<<dim3(SS / NQ, BB), 512, FUSED_SMEM>>>(
        query, in_w, in_b, mask_w, kv, out_w, out_b, mean_out, out);
}

// round 17
// speedup vs baseline: 6.0125x; 1.0197x over previous
#include <cuda_runtime.h>
#include <cuda_fp16.h>

#define BB 4
#define SS 1024
#define EE 1024
#define HH 16
#define DD 64
#define NQ 32
#define SCALE 0.125f
#define NBLK (BB * (SS / NQ))   // 128 fused blocks
#define NEGINF __int_as_float(0xff800000)

__device__ unsigned int g_bar;  // monotonic grid barrier (no reset needed)

// fused smem layout (bytes):
#define SMB_CTX    132096                // s_scores f32 [32][1032] before it
#define SMB_KT     (SMB_CTX + 66048)     // 198144; [3][64][72] f16 = 27648
#define SMB_KEEP   (SMB_KT + 27648)      // 225792
#define SMB_INV    (SMB_KEEP + 4096)     // 229888
#define FUSED_SMEM (SMB_INV + 128)       // 230016 <= 232448

#define KV_SMEM (2 * 64 * 264 * 2)       // 67584
#define KTB 9216                          // bytes per ring buffer (64*72*2)

__device__ __forceinline__ void mma16816(float c[4], const unsigned a[4],
                                         const unsigned bf[2]) {
    asm volatile(
        "mma.sync.aligned.m16n8k16.row.col.f32.f16.f16.f32 "
        "{%0,%1,%2,%3}, {%4,%5,%6,%7}, {%8,%9}, {%0,%1,%2,%3};\n"
        : "+f"(c[0]), "+f"(c[1]), "+f"(c[2]), "+f"(c[3])
        : "r"(a[0]), "r"(a[1]), "r"(a[2]), "r"(a[3]), "r"(bf[0]), "r"(bf[1]));
}

__device__ __forceinline__ unsigned su32(const void* p) {
    unsigned a;
    asm("{ .reg .u64 t; cvta.to.shared.u64 t, %1; cvt.u32.u64 %0, t; }"
        : "=r"(a) : "l"(p));
    return a;
}

__device__ __forceinline__ void cp16(unsigned dst, const void* src) {
    asm volatile("cp.async.ca.shared.global [%0], [%1], 16;\n"
                 :: "r"(dst), "l"(src));
}
#define CP_COMMIT() asm volatile("cp.async.commit_group;\n")
#define CP_WAIT0()  asm volatile("cp.async.wait_group 0;\n")
#define CP_WAIT1()  asm volatile("cp.async.wait_group 1;\n")

__device__ __forceinline__ void ldmx4(unsigned r[4], unsigned a) {
    asm volatile("ldmatrix.sync.aligned.m8n8.x4.shared.b16 {%0,%1,%2,%3}, [%4];\n"
        : "=r"(r[0]), "=r"(r[1]), "=r"(r[2]), "=r"(r[3]) : "r"(a));
}
__device__ __forceinline__ void ldmx4t(unsigned r[4], unsigned a) {
    asm volatile("ldmatrix.sync.aligned.m8n8.x4.trans.shared.b16 {%0,%1,%2,%3}, [%4];\n"
        : "=r"(r[0]), "=r"(r[1]), "=r"(r[2]), "=r"(r[3]) : "r"(a));
}

// ============================================================================
// P1: K/V projection via HMMA -> fp16 into the (dead) output region.
// ============================================================================
__global__ void __launch_bounds__(256, 2)
kv_proj_kernel(const float* __restrict__ key,
               const float* __restrict__ value,
               const float* __restrict__ in_w,
               const float* __restrict__ in_b,
               __half* __restrict__ kv)
{
    extern __shared__ char sm[];
    __half* Xs = (__half*)sm;                  // [64][264]
    __half* Ws = Xs + 64 * 264;                // [64][264]

    const int which = blockIdx.x >> 4;         // 0=k, 1=v
    const int s0 = (blockIdx.x & 15) * 64;
    const int h = blockIdx.y, b = blockIdx.z;
    const float* X = (which ? value : key) + (size_t)b * SS * EE;
    const int woff = (which ? 2048 : 1024) + h * 64;

    const int tid = threadIdx.x;
    const int wid = tid >> 5, lane = tid & 31;
    const int g = lane >> 2, t = lane & 3;
    const int mw = (wid >> 1) * 16;
    const int nh = (wid & 1) * 32;

    float acc[4][4];
    #pragma unroll
    for (int i = 0; i < 4; i++)
        #pragma unroll
        for (int j = 0; j < 4; j++) acc[i][j] = 0.0f;

    const unsigned aB = su32(Xs) + (mw + (lane & 15))*528 + ((lane & 16) ? 16 : 0);
    const unsigned bB0 = su32(Ws) + (nh + (lane & 7))*528
                         + (((lane >> 3) & 1) ? 16 : 0)
                         + ((lane & 16) ? 528*8 : 0);
    const unsigned bB1 = bB0 + 16*528;

    for (int e0 = 0; e0 < 1024; e0 += 256) {
        __syncthreads();
        for (int i = tid; i < 4096; i += 256) {
            const int r = i >> 6, c4 = i & 63;
            float4 v = *(const float4*)&X[(size_t)(s0 + r) * 1024 + e0 + c4 * 4];
            *(__half2*)&Xs[r*264 + c4*4]     = __floats2half2_rn(v.x, v.y);
            *(__half2*)&Xs[r*264 + c4*4 + 2] = __floats2half2_rn(v.z, v.w);
        }
        for (int i = tid; i < 4096; i += 256) {
            const int r = i >> 6, c4 = i & 63;
            float4 v = *(const float4*)&in_w[(size_t)(woff + r) * 1024 + e0 + c4 * 4];
            *(__half2*)&Ws[r*264 + c4*4]     = __floats2half2_rn(v.x, v.y);
            *(__half2*)&Ws[r*264 + c4*4 + 2] = __floats2half2_rn(v.z, v.w);
        }
        __syncthreads();

        #pragma unroll
        for (int ks = 0; ks < 16; ks++) {
            unsigned a[4];
            ldmx4(a, aB + ks*32);
            unsigned bb[4];
            ldmx4(bb, bB0 + ks*32);              // n tiles nh, nh+8
            mma16816(acc[0], a, bb);
            mma16816(acc[1], a, bb + 2);
            ldmx4(bb, bB1 + ks*32);              // n tiles nh+16, nh+24
            mma16816(acc[2], a, bb);
            mma16816(acc[3], a, bb + 2);
        }
    }

    __half* dst = kv + (size_t)which * (BB*HH*SS*DD)
                     + ((size_t)(b * HH + h) * SS) * DD;
    #pragma unroll
    for (int ns = 0; ns < 4; ns++) {
        const int n = nh + ns * 8;
        const float b0 = in_b[woff + n + t*2];
        const float b1 = in_b[woff + n + t*2 + 1];
        *(__half2*)&dst[(size_t)(s0+mw+g)*DD + n + t*2] =
            __floats2half2_rn(acc[ns][0] + b0, acc[ns][1] + b1);
        *(__half2*)&dst[(size_t)(s0+mw+g+8)*DD + n + t*2] =
            __floats2half2_rn(acc[ns][2] + b0, acc[ns][3] + b1);
    }
}

// ============================================================================
// P2: fused attention + out-projection; ring-3 single-barrier pipeline.
// ============================================================================
__global__ void __launch_bounds__(512, 1)
fused_attn_kernel(const float* __restrict__ query,
                  const float* __restrict__ in_w,
                  const float* __restrict__ in_b,
                  const unsigned int* __restrict__ mask_w,
                  const __half* __restrict__ kv,
                  const float* __restrict__ out_w,
                  const float* __restrict__ out_b,
                  float* __restrict__ mean_out,
                  float* __restrict__ out)
{
    extern __shared__ char smem[];
    float*  s_scores = (float*)smem;                 // [32][1032] f32
    __half* s_ctx    = (__half*)(smem + SMB_CTX);    // [32][1032] f16: q16all -> ctx
    __half* s_kt     = (__half*)(smem + SMB_KT);     // [3][64][72] f16 ring
    float*  s_keep   = (float*)(smem + SMB_KEEP);
    float*  s_inv    = (float*)(smem + SMB_INV);

    const int qt = blockIdx.x, b = blockIdx.y;
    const int q0 = qt * NQ;
    const int tid = threadIdx.x;
    const int wid = tid >> 5, lane = tid & 31;
    const int g = lane >> 2, t = lane & 3;
    const int mw = (wid >> 3) * 16;   // 0|16
    const int nw = (wid & 7) * 8;     // 0..56
    const int str = tid >> 3;         // stage row 0..63
    const int stc = tid & 7;          // stage 16B chunk 0..7

    // per-thread bases (ring slot added per-iteration)
    const int lane15 = lane & 15, lane7 = lane & 7;
    const unsigned cxA = su32(s_ctx) + (mw + lane15)*2064 + ((lane & 16) ? 16 : 0);
    const unsigned pA  = su32(s_scores) + (mw + lane15)*4128 + ((lane & 16) ? 16 : 0);
    const unsigned stgb = su32(s_kt) + str*144 + stc*16;
    const unsigned kBb  = su32(s_kt) + (nw + lane7)*144 + ((lane >> 3) & 3)*16;
    const unsigned vTb  = su32(s_kt) + lane*144 + nw*2;

    for (int i = tid; i < 1024; i += 512)
        s_keep[i] = (mask_w[b * SS + i] != 0u) ? 1.0f : 0.0f;

    int ring = 0;   // ring slot of the next tile to consume

    // pipeline prologue: K tiles 0,1 of head 0 -> slots 0,1
    {
        const __half* Kb0 = kv + ((size_t)(b * HH) * SS) * DD;
        cp16(stgb,       &Kb0[(size_t)str*64 + stc*8]);        CP_COMMIT();
        cp16(stgb + KTB, &Kb0[(size_t)(64 + str)*64 + stc*8]); CP_COMMIT();
    }

    // ======== upfront Q-proj for ALL heads -> s_ctx (staging in scores region)
    {
        __half* q16a = (__half*)smem;            // [32][1032]
        __half* wst  = (__half*)(smem + 66048);  // [64][264] per-k0 chunk
        for (int i = tid; i < 8192; i += 512) {
            const int r = i >> 8, c4 = i & 255;
            float4 v = *(const float4*)&query[((size_t)(b*SS)+q0+r)*1024 + c4*4];
            *(__half2*)&q16a[r*1032 + c4*4]     = __floats2half2_rn(v.x, v.y);
            *(__half2*)&q16a[r*1032 + c4*4 + 2] = __floats2half2_rn(v.z, v.w);
        }
        __syncthreads();

        const unsigned qA = su32(q16a) + (mw + lane15)*2064 + ((lane & 16) ? 16 : 0);
        const unsigned wB = su32(wst) + (nw + lane7)*528 + ((lane >> 3) & 3)*16;

        for (int n0 = 0; n0 < 1024; n0 += 64) {
            float qc0[4] = {0.f,0.f,0.f,0.f}, qc1[4] = {0.f,0.f,0.f,0.f};

            for (int k0 = 0; k0 < 1024; k0 += 256) {
                __syncthreads();
                for (int i = tid; i < 4096; i += 512) {
                    const int r = i >> 6, c4 = i & 63;
                    float4 v = *(const float4*)&in_w[(size_t)(n0 + r)*1024 + k0 + c4*4];
                    *(__half2*)&wst[r*264 + c4*4]     = __floats2half2_rn(v.x, v.y);
                    *(__half2*)&wst[r*264 + c4*4 + 2] = __floats2half2_rn(v.z, v.w);
                }
                __syncthreads();

                #pragma unroll
                for (int ks2 = 0; ks2 < 8; ks2++) {
                    unsigned aa[4], ab[4], bb[4];
                    ldmx4(aa, qA + k0*2 + ks2*64);
                    ldmx4(ab, qA + k0*2 + ks2*64 + 32);
                    ldmx4(bb, wB + ks2*64);
                    mma16816(qc0, aa, bb);
                    mma16816(qc1, ab, bb + 2);
                }
            }
            const int col = n0 + nw + t*2;
            const float bb0 = in_b[col], bb1 = in_b[col+1];
            *(__half2*)&s_ctx[(mw+g)*1032 + col] =
                __floats2half2_rn(qc0[0]+qc1[0]+bb0, qc0[1]+qc1[1]+bb1);
            *(__half2*)&s_ctx[(mw+g+8)*1032 + col] =
                __floats2half2_rn(qc0[2]+qc1[2]+bb0, qc0[3]+qc1[3]+bb1);
        }
        __syncthreads();
    }

    for (int h = 0; h < HH; h++) {
        const __half* Kb = kv + ((size_t)(b * HH + h) * SS) * DD;
        const __half* Vb = Kb + (size_t)(BB*HH*SS*DD);

        // hoisted A-frags (Q of head h) from s_ctx cols h*64
        unsigned aq[4][4];
        #pragma unroll
        for (int ks = 0; ks < 4; ks++)
            ldmx4(aq[ks], cxA + h*128 + ks*32);

        // ---------- scores: ring-3, ONE barrier per tile ----------
        for (int kt = 0; kt < 16; kt++) {
            CP_WAIT1();
            __syncthreads();                    // tile visible + ring[-1] free

            // prefetch tile kt+2 into the slot consumed 1 iter ago
            int pslot = ring + 2; if (pslot >= 3) pslot -= 3;
            const unsigned dst = stgb + pslot*KTB;
            if (kt + 2 < 16) {
                cp16(dst, &Kb[(size_t)((kt+2)*64 + str)*64 + stc*8]);
            } else if (kt == 14) {
                cp16(dst, &Vb[(size_t)str*64 + stc*8]);
            } else {
                cp16(dst, &Vb[(size_t)(64 + str)*64 + stc*8]);
            }
            CP_COMMIT();

            const unsigned kB = kBb + ring*KTB;
            float sc0[4] = {0.f,0.f,0.f,0.f}, sc1[4] = {0.f,0.f,0.f,0.f};
            float sc2[4] = {0.f,0.f,0.f,0.f}, sc3[4] = {0.f,0.f,0.f,0.f};
            unsigned bb[4], bbb[4];
            ldmx4(bb, kB);
            ldmx4(bbb, kB + 64);
            mma16816(sc0, aq[0], bb);
            mma16816(sc1, aq[1], bb + 2);
            mma16816(sc2, aq[2], bbb);
            mma16816(sc3, aq[3], bbb + 2);

            const int kg = kt*64 + nw + t*2;
            const float kf0 = s_keep[kg], kf1 = s_keep[kg+1];
            const int r0 = mw + g, r1 = mw + g + 8;
            float v00 = (sc0[0]+sc1[0]+sc2[0]+sc3[0])*SCALE + (float)(q0 + r0 - kg);
            float v01 = (sc0[1]+sc1[1]+sc2[1]+sc3[1])*SCALE + (float)(q0 + r0 - kg - 1);
            float v10 = (sc0[2]+sc1[2]+sc2[2]+sc3[2])*SCALE + (float)(q0 + r1 - kg);
            float v11 = (sc0[3]+sc1[3]+sc2[3]+sc3[3])*SCALE + (float)(q0 + r1 - kg - 1);
            v00 = (kf0 != 0.f) ? v00 : NEGINF;
            v01 = (kf1 != 0.f) ? v01 : NEGINF;
            v10 = (kf0 != 0.f) ? v10 : NEGINF;
            v11 = (kf1 != 0.f) ? v11 : NEGINF;
            *(float2*)&s_scores[r0*1032 + kg] = make_float2(v00, v01);
            *(float2*)&s_scores[r1*1032 + kg] = make_float2(v10, v11);

            ring++; if (ring == 3) ring = 0;
        }
        __syncthreads();   // scores visible to softmax

        // ---------- softmax (warp/row, single smem read) ----------
        for (int r = wid; r < 32; r += 16) {
            float* srow = s_scores + r * 1032;
            __half* prow = (__half*)srow;

            float pvv[32];
            #pragma unroll
            for (int i = 0; i < 32; i++) pvv[i] = srow[lane + 32*i];

            float mx = NEGINF;
            #pragma unroll
            for (int i = 0; i < 32; i++) mx = fmaxf(mx, pvv[i]);
            #pragma unroll
            for (int m = 16; m >= 1; m >>= 1)
                mx = fmaxf(mx, __shfl_xor_sync(0xffffffffu, mx, m));

            float sum = 0.f;
            #pragma unroll
            for (int i = 0; i < 32; i++) {
                const float p = __expf(pvv[i] - mx);
                pvv[i] = p; sum += p;
            }
            #pragma unroll
            for (int m = 16; m >= 1; m >>= 1)
                sum += __shfl_xor_sync(0xffffffffu, sum, m);

            const float inv = 1.0f / sum;
            if (lane == 0) s_inv[r] = inv;

            #pragma unroll
            for (int i = 0; i < 32; i++)
                prow[lane + 32*i] = __float2half(pvv[i]);

            float* mrow = mean_out + ((size_t)(b*SS) + q0 + r) * SS;
            const float msc = inv * 0.0625f;
            if (h == 0) {
                #pragma unroll
                for (int i = 0; i < 32; i++) mrow[lane + 32*i] = pvv[i] * msc;
            } else {
                #pragma unroll
                for (int i = 0; i < 32; i++) mrow[lane + 32*i] += pvv[i] * msc;
            }
        }

        // ---------- PV: ring-3, ONE barrier per tile ----------
        {
            float ca0[4] = {0.f,0.f,0.f,0.f}, ca1[4] = {0.f,0.f,0.f,0.f};
            float ca2[4] = {0.f,0.f,0.f,0.f}, ca3[4] = {0.f,0.f,0.f,0.f};

            for (int vt = 0; vt < 16; vt++) {
                if (vt == 15 && h == HH-1) CP_WAIT0(); else CP_WAIT1();
                __syncthreads();

                int pslot = ring + 2; if (pslot >= 3) pslot -= 3;
                const unsigned dst = stgb + pslot*KTB;
                if (vt + 2 < 16) {
                    cp16(dst, &Vb[(size_t)((vt+2)*64 + str)*64 + stc*8]); CP_COMMIT();
                } else if (h + 1 < HH) {
                    const __half* Kbn = Kb + (size_t)SS * DD;   // next head's K
                    if (vt == 14) { cp16(dst, &Kbn[(size_t)str*64 + stc*8]); CP_COMMIT(); }
                    else          { cp16(dst, &Kbn[(size_t)(64 + str)*64 + stc*8]); CP_COMMIT(); }
                }

                const unsigned vT = vTb + ring*KTB;
                const unsigned pa = pA + vt*128;

                unsigned a0[4], a1[4], a2[4], a3[4], b0[4], b1[4];
                ldmx4(a0, pa);
                ldmx4(a1, pa + 32);
                ldmx4(a2, pa + 64);
                ldmx4(a3, pa + 96);
                ldmx4t(b0, vT);
                ldmx4t(b1, vT + 32*144);
                mma16816(ca0, a0, b0);
                mma16816(ca1, a1, b0 + 2);
                mma16816(ca2, a2, b1);
                mma16816(ca3, a3, b1 + 2);

                ring++; if (ring == 3) ring = 0;
            }

            const int r0 = mw + g, r1 = mw + g + 8;
            const float i0 = s_inv[r0], i1 = s_inv[r1];
            *(__half2*)&s_ctx[r0*1032 + h*64 + nw + t*2] =
                __floats2half2_rn((ca0[0]+ca1[0]+ca2[0]+ca3[0])*i0,
                                  (ca0[1]+ca1[1]+ca2[1]+ca3[1])*i0);
            *(__half2*)&s_ctx[r1*1032 + h*64 + nw + t*2] =
                __floats2half2_rn((ca0[2]+ca1[2]+ca2[2]+ca3[2])*i1,
                                  (ca0[3]+ca1[3]+ca2[3]+ca3[3])*i1);
        }
        __syncthreads();
    }

    // ==================== grid barrier ====================
    if (tid == 0) {
        __threadfence();
        const unsigned int old = atomicAdd(&g_bar, 1u);
        const unsigned int target = (old / NBLK + 1u) * NBLK;
        while (atomicAdd(&g_bar, 0u) < target) { }
    }
    __syncthreads();

    // ==================== out-proj: out = ctx @ Wo^T + bias ====================
    {
        __half* woS = (__half*)smem;              // [64][1032] fp16 (scores dead)
        const unsigned wB = su32(woS) + (nw + lane7)*2064 + ((lane >> 3) & 3)*16;

        for (int n0 = 0; n0 < 1024; n0 += 64) {
            __syncthreads();
            for (int i = tid; i < 16384; i += 512) {
                const int r = i >> 8, c4 = i & 255;
                float4 v = *(const float4*)&out_w[(size_t)(n0 + r)*1024 + c4*4];
                *(__half2*)&woS[r*1032 + c4*4]     = __floats2half2_rn(v.x, v.y);
                *(__half2*)&woS[r*1032 + c4*4 + 2] = __floats2half2_rn(v.z, v.w);
            }
            __syncthreads();

            float oc0[4] = {0.f,0.f,0.f,0.f}, oc1[4] = {0.f,0.f,0.f,0.f};
            #pragma unroll 4
            for (int ks2 = 0; ks2 < 32; ks2++) {
                unsigned aa[4], ab[4], bb[4];
                ldmx4(aa, cxA + ks2*64);
                ldmx4(ab, cxA + ks2*64 + 32);
                ldmx4(bb, wB + ks2*64);
                mma16816(oc0, aa, bb);
                mma16816(oc1, ab, bb + 2);
            }

            const int col = n0 + nw + t*2;
            const float bb0 = out_b[col], bb1 = out_b[col+1];
            const int r0 = mw + g, r1 = mw + g + 8;
            *(float2*)&out[((size_t)(b*SS)+q0+r0)*1024 + col] =
                make_float2(oc0[0]+oc1[0]+bb0, oc0[1]+oc1[1]+bb1);
            *(float2*)&out[((size_t)(b*SS)+q0+r1)*1024 + col] =
                make_float2(oc0[2]+oc1[2]+bb0, oc0[3]+oc1[3]+bb1);
        }
    }
}

// ============================================================================
extern "C" void kernel_launch(void* const* d_in, const int* in_sizes, int n_in,
                              void* d_out, int out_size)
{
    const float* query = (const float*)d_in[0];
    const float* key   = (const float*)d_in[1];
    const float* value = (const float*)d_in[2];
    const unsigned int* mask_w = (const unsigned int*)d_in[3];
    const float* in_w  = (const float*)d_in[4];
    const float* in_b  = (const float*)d_in[5];
    const float* out_w = (const float*)d_in[6];
    const float* out_b = (const float*)d_in[7];

    float* out      = (float*)d_out;                 // (B,S,E); kv fp16 until out-proj
    float* mean_out = out + (size_t)BB * SS * EE;    // (B,S,S)
    __half* kv      = (__half*)d_out;

    cudaFuncSetAttribute(fused_attn_kernel,
                         cudaFuncAttributeMaxDynamicSharedMemorySize, FUSED_SMEM);
    cudaFuncSetAttribute(kv_proj_kernel,
                         cudaFuncAttributeMaxDynamicSharedMemorySize, KV_SMEM);

    kv_proj_kernel<<<dim3(32, HH, BB), 256, KV_SMEM>>>(key, value, in_w, in_b, kv);

    fused_attn_kernel<<<dim3(SS / NQ, BB), 512, FUSED_SMEM>>>(
        query, in_w, in_b, mask_w, kv, out_w, out_b, mean_out, out);
}